// round 3
// baseline (speedup 1.0000x reference)
#include <cuda_runtime.h>
#include <math.h>

#define BB   4
#define SS   1024
#define HIDN 768
#define AHN  384
#define NH   6
#define DDIM 64
#define KSZ  9
#define RPAD 4
#define NROWS (BB*SS)   /* 4096 */
#define TI   32         /* query rows per attention block */

// ---------------- scratch (static device globals: allocation-free) ----------
__device__ float g_mq [NROWS*AHN];
__device__ float g_mk [NROWS*AHN];
__device__ float g_mv [NROWS*AHN];
__device__ float g_co [NROWS*AHN];
__device__ float g_dw [NROWS*HIDN];
__device__ float g_mkc[NROWS*AHN];
__device__ float g_ca [NROWS*AHN];
__device__ float g_ck [NROWS*NH*KSZ];
__device__ float g_tdsm[BB*SS];

struct Jobs4 {
    const float* A[4];
    const float* B[4];
    const float* bias[4];
    float*       C[4];
};

// ---------------- batched SGEMM: 128x128 tile, 8x8 microtile, dbl-buffered --
// BT=false: B stored (K,N).  BT=true: B stored (N,K).
// Requires M%128==0, N%128==0, K%16==0.
template<bool BT>
__global__ __launch_bounds__(256, 2)
void sgemm3(Jobs4 jobs, int M, int N, int K) {
    __shared__ float As[2][16 * 132];
    __shared__ float Bs[2][16 * 132];
    const float* __restrict__ A    = jobs.A[blockIdx.z];
    const float* __restrict__ Bm   = jobs.B[blockIdx.z];
    const float* __restrict__ bias = jobs.bias[blockIdx.z];
    float* __restrict__       C    = jobs.C[blockIdx.z];
    const int tid = threadIdx.x;
    const int tx = tid & 15, ty = tid >> 4;
    const int bm = blockIdx.y * 128, bn = blockIdx.x * 128;

    float4 pa[2], pb[2];
    float acc[8][8] = {};

    const int am  = tid >> 2, akq = tid & 3;          // A: m=am+64l, k=4akq
    const int bk  = tid >> 5, bnq = tid & 31;         // B nonT: k=bk+8l, n=4bnq
    const int btn = tid >> 2, btk = tid & 3;          // B T: n=btn+64l, k=4btk

    const int nT = K / 16;

    // prologue: load tile 0
#pragma unroll
    for (int l = 0; l < 2; l++)
        pa[l] = *(const float4*)&A[(size_t)(bm + am + 64 * l) * K + 4 * akq];
    if (BT) {
#pragma unroll
        for (int l = 0; l < 2; l++)
            pb[l] = *(const float4*)&Bm[(size_t)(bn + btn + 64 * l) * K + 4 * btk];
    } else {
#pragma unroll
        for (int l = 0; l < 2; l++)
            pb[l] = *(const float4*)&Bm[(size_t)(bk + 8 * l) * N + bn + 4 * bnq];
    }
#pragma unroll
    for (int l = 0; l < 2; l++) {
        int m = am + 64 * l;
        As[0][(4 * akq + 0) * 132 + m] = pa[l].x;
        As[0][(4 * akq + 1) * 132 + m] = pa[l].y;
        As[0][(4 * akq + 2) * 132 + m] = pa[l].z;
        As[0][(4 * akq + 3) * 132 + m] = pa[l].w;
    }
    if (BT) {
#pragma unroll
        for (int l = 0; l < 2; l++) {
            int n = btn + 64 * l;
            Bs[0][(4 * btk + 0) * 132 + n] = pb[l].x;
            Bs[0][(4 * btk + 1) * 132 + n] = pb[l].y;
            Bs[0][(4 * btk + 2) * 132 + n] = pb[l].z;
            Bs[0][(4 * btk + 3) * 132 + n] = pb[l].w;
        }
    } else {
#pragma unroll
        for (int l = 0; l < 2; l++)
            *(float4*)&Bs[0][(bk + 8 * l) * 132 + 4 * bnq] = pb[l];
    }
    __syncthreads();

    for (int kt = 1; kt < nT; kt++) {
        const int k0 = kt * 16;
#pragma unroll
        for (int l = 0; l < 2; l++)
            pa[l] = *(const float4*)&A[(size_t)(bm + am + 64 * l) * K + k0 + 4 * akq];
        if (BT) {
#pragma unroll
            for (int l = 0; l < 2; l++)
                pb[l] = *(const float4*)&Bm[(size_t)(bn + btn + 64 * l) * K + k0 + 4 * btk];
        } else {
#pragma unroll
            for (int l = 0; l < 2; l++)
                pb[l] = *(const float4*)&Bm[(size_t)(k0 + bk + 8 * l) * N + bn + 4 * bnq];
        }
        const int cb = (kt - 1) & 1;
#pragma unroll
        for (int k = 0; k < 16; k++) {
            float4 a0 = *(const float4*)&As[cb][k * 132 + ty * 8];
            float4 a1 = *(const float4*)&As[cb][k * 132 + ty * 8 + 4];
            float4 b0 = *(const float4*)&Bs[cb][k * 132 + tx * 8];
            float4 b1 = *(const float4*)&Bs[cb][k * 132 + tx * 8 + 4];
            float av[8] = {a0.x, a0.y, a0.z, a0.w, a1.x, a1.y, a1.z, a1.w};
            float bv[8] = {b0.x, b0.y, b0.z, b0.w, b1.x, b1.y, b1.z, b1.w};
#pragma unroll
            for (int u = 0; u < 8; u++)
#pragma unroll
                for (int v = 0; v < 8; v++) acc[u][v] += av[u] * bv[v];
        }
        const int sb = kt & 1;
#pragma unroll
        for (int l = 0; l < 2; l++) {
            int m = am + 64 * l;
            As[sb][(4 * akq + 0) * 132 + m] = pa[l].x;
            As[sb][(4 * akq + 1) * 132 + m] = pa[l].y;
            As[sb][(4 * akq + 2) * 132 + m] = pa[l].z;
            As[sb][(4 * akq + 3) * 132 + m] = pa[l].w;
        }
        if (BT) {
#pragma unroll
            for (int l = 0; l < 2; l++) {
                int n = btn + 64 * l;
                Bs[sb][(4 * btk + 0) * 132 + n] = pb[l].x;
                Bs[sb][(4 * btk + 1) * 132 + n] = pb[l].y;
                Bs[sb][(4 * btk + 2) * 132 + n] = pb[l].z;
                Bs[sb][(4 * btk + 3) * 132 + n] = pb[l].w;
            }
        } else {
#pragma unroll
            for (int l = 0; l < 2; l++)
                *(float4*)&Bs[sb][(bk + 8 * l) * 132 + 4 * bnq] = pb[l];
        }
        __syncthreads();
    }
    {
        const int cb = (nT - 1) & 1;
#pragma unroll
        for (int k = 0; k < 16; k++) {
            float4 a0 = *(const float4*)&As[cb][k * 132 + ty * 8];
            float4 a1 = *(const float4*)&As[cb][k * 132 + ty * 8 + 4];
            float4 b0 = *(const float4*)&Bs[cb][k * 132 + tx * 8];
            float4 b1 = *(const float4*)&Bs[cb][k * 132 + tx * 8 + 4];
            float av[8] = {a0.x, a0.y, a0.z, a0.w, a1.x, a1.y, a1.z, a1.w};
            float bv[8] = {b0.x, b0.y, b0.z, b0.w, b1.x, b1.y, b1.z, b1.w};
#pragma unroll
            for (int u = 0; u < 8; u++)
#pragma unroll
                for (int v = 0; v < 8; v++) acc[u][v] += av[u] * bv[v];
        }
    }

    float4 bb0 = make_float4(0.f, 0.f, 0.f, 0.f), bb1 = bb0;
    if (bias) {
        bb0 = *(const float4*)&bias[bn + tx * 8];
        bb1 = *(const float4*)&bias[bn + tx * 8 + 4];
    }
#pragma unroll
    for (int u = 0; u < 8; u++) {
        size_t row = (size_t)(bm + ty * 8 + u) * N + bn + tx * 8;
        float4 o0 = make_float4(acc[u][0] + bb0.x, acc[u][1] + bb0.y,
                                acc[u][2] + bb0.z, acc[u][3] + bb0.w);
        float4 o1 = make_float4(acc[u][4] + bb1.x, acc[u][5] + bb1.y,
                                acc[u][6] + bb1.z, acc[u][7] + bb1.w);
        *(float4*)&C[row]     = o0;
        *(float4*)&C[row + 4] = o1;
    }
}

// ---------------- small guarded SGEMM (for N=54 conv-kernel layer) ----------
template<bool BT, bool BIAS>
__global__ void sgemm_small(const float* __restrict__ A, const float* __restrict__ Bm,
                            const float* __restrict__ bias, float* __restrict__ C,
                            int M, int N, int K) {
    __shared__ float As[16][64];
    __shared__ float Bs[16][64];
    const int tid = threadIdx.x;
    const int tx = tid & 15, ty = tid >> 4;
    const int bm = blockIdx.y * 64, bn = blockIdx.x * 64;
    float acc[4][4] = {};
    for (int k0 = 0; k0 < K; k0 += 16) {
#pragma unroll
        for (int l = 0; l < 4; l++) {
            int idx = tid + l * 256;
            int m = idx >> 4, k = idx & 15;
            As[k][m] = A[(size_t)(bm + m) * K + (k0 + k)];
        }
#pragma unroll
        for (int l = 0; l < 4; l++) {
            int idx = tid + l * 256;
            if (BT) {
                int n = idx >> 4, k = idx & 15;
                Bs[k][n] = (bn + n < N) ? Bm[(size_t)(bn + n) * K + (k0 + k)] : 0.f;
            } else {
                int k = idx >> 6, n = idx & 63;
                Bs[k][n] = (bn + n < N) ? Bm[(size_t)(k0 + k) * N + (bn + n)] : 0.f;
            }
        }
        __syncthreads();
#pragma unroll
        for (int k = 0; k < 16; k++) {
            float a[4], bv[4];
#pragma unroll
            for (int u = 0; u < 4; u++) a[u]  = As[k][ty * 4 + u];
#pragma unroll
            for (int v = 0; v < 4; v++) bv[v] = Bs[k][tx * 4 + v];
#pragma unroll
            for (int u = 0; u < 4; u++)
#pragma unroll
                for (int v = 0; v < 4; v++) acc[u][v] += a[u] * bv[v];
        }
        __syncthreads();
    }
#pragma unroll
    for (int u = 0; u < 4; u++) {
        int m = bm + ty * 4 + u;
#pragma unroll
        for (int v = 0; v < 4; v++) {
            int n = bn + tx * 4 + v;
            if (n < N) C[(size_t)m * N + n] = acc[u][v] + (BIAS ? bias[n] : 0.f);
        }
    }
}

// ---------------- depthwise conv over sequence (K input) --------------------
__global__ void dwconv_kernel(const float* __restrict__ Kin,
                              const float* __restrict__ dw_w,
                              float* __restrict__ out) {
    int e = blockIdx.x * 256 + threadIdx.x;
    if (e >= NROWS * HIDN) return;
    int c = e % HIDN;
    int bs = e / HIDN;
    int s = bs % SS, b = bs / SS;
    float acc = 0.f;
#pragma unroll
    for (int t = 0; t < KSZ; t++) {
        int sp = s + t - RPAD;
        if (sp >= 0 && sp < SS)
            acc += Kin[((size_t)b * SS + sp) * HIDN + c] * dw_w[c * KSZ + t];
    }
    out[e] = acc;
}

// ---------------- elementwise multiply --------------------------------------
__global__ void emul_kernel(const float* __restrict__ a, const float* __restrict__ b,
                            float* __restrict__ c, int n) {
    int i = blockIdx.x * 256 + threadIdx.x;
    if (i < n) c[i] = a[i] * b[i];
}

// ---------------- per (b,s,h) softmax over KS kernel taps --------------------
__global__ void ck_softmax_kernel(float* __restrict__ ck) {
    int r = blockIdx.x * 256 + threadIdx.x;
    if (r >= NROWS * NH) return;
    int row = r / NH, h = r % NH;
    float* p = ck + (size_t)row * (NH * KSZ) + h * KSZ;
    float mx = p[0];
#pragma unroll
    for (int t = 1; t < KSZ; t++) mx = fmaxf(mx, p[t]);
    float e[KSZ]; float s = 0.f;
#pragma unroll
    for (int t = 0; t < KSZ; t++) { e[t] = __expf(p[t] - mx); s += e[t]; }
    float inv = 1.f / s;
#pragma unroll
    for (int t = 0; t < KSZ; t++) p[t] = e[t] * inv;
}

// ---------------- dynamic-span conv output (second half of out) -------------
__global__ void conv_out_kernel(const float* __restrict__ co,
                                const float* __restrict__ ck,
                                float* __restrict__ out) {
    int r = blockIdx.x;          // (b*S+s)
    int t = threadIdx.x;         // 0..383 = h*64+d
    int h = t >> 6;
    int b = r / SS, s = r % SS;
    __shared__ float cks[NH * KSZ];
    if (t < NH * KSZ) cks[t] = ck[(size_t)r * (NH * KSZ) + t];
    __syncthreads();
    float acc = 0.f;
#pragma unroll
    for (int k = 0; k < KSZ; k++) {
        int sp = s + k - RPAD;
        if (sp >= 0 && sp < SS)
            acc += co[((size_t)b * SS + sp) * AHN + t] * cks[h * KSZ + k];
    }
    out[(size_t)r * 768 + AHN + t] = acc;
}

// ---------------- td softmax (key-mask only: independent of i,h) ------------
__global__ void tdsm_kernel(const float* __restrict__ td, const int* __restrict__ mask,
                            float* __restrict__ out) {
    int b = blockIdx.x;
    int tid = threadIdx.x, lane = tid & 31, wid = tid >> 5;
    __shared__ float buf[SS];
    __shared__ float red[8];
    float ss = 0.f;
    for (int j = tid; j < SS; j += 256) { float v = td[b * SS + j]; ss += v * v; }
#pragma unroll
    for (int o = 16; o > 0; o >>= 1) ss += __shfl_xor_sync(0xffffffffu, ss, o);
    if (lane == 0) red[wid] = ss;
    __syncthreads();
    float tot = 0.f;
#pragma unroll
    for (int w = 0; w < 8; w++) tot += red[w];
    float nrm = fmaxf(sqrtf(tot), 1e-12f);
    __syncthreads();
    float mx = -3.4e38f;
    for (int j = tid; j < SS; j += 256) {
        float v = mask[b * SS + j] ? td[b * SS + j] / nrm : -1e4f;
        buf[j] = v;
        mx = fmaxf(mx, v);
    }
#pragma unroll
    for (int o = 16; o > 0; o >>= 1) mx = fmaxf(mx, __shfl_xor_sync(0xffffffffu, mx, o));
    if (lane == 0) red[wid] = mx;
    __syncthreads();
    float bmx = red[0];
#pragma unroll
    for (int w = 1; w < 8; w++) bmx = fmaxf(bmx, red[w]);
    __syncthreads();
    float sum = 0.f;
    for (int j = tid; j < SS; j += 256) {
        float e = expf(buf[j] - bmx);
        buf[j] = e;
        sum += e;
    }
#pragma unroll
    for (int o = 16; o > 0; o >>= 1) sum += __shfl_xor_sync(0xffffffffu, sum, o);
    if (lane == 0) red[wid] = sum;
    __syncthreads();
    float bsum = 0.f;
#pragma unroll
    for (int w = 0; w < 8; w++) bsum += red[w];
    float inv = 1.f / bsum;
    __syncthreads();
    for (int j = tid; j < SS; j += 256) out[b * SS + j] = buf[j] * inv;
}

// ---------------- attention: 32 query rows per block ------------------------
// block = (i-tile, h, b); 256 threads = 8 warps; warp w owns rows 4w..4w+3.
// Scores/probs stored TRANSPOSED: addr(r, j) = r*1056 + (j>>5)*33 + (j&31),
// so lane owns contiguous j = lane*32 .. lane*32+31 in phase 2.
__global__ __launch_bounds__(256)
void attn_kernel(const float* __restrict__ mq, const float* __restrict__ mk,
                 const float* __restrict__ mv, const int* __restrict__ mask,
                 const float* __restrict__ tdsm, const float* __restrict__ gammas,
                 float* __restrict__ out) {
    extern __shared__ float sm[];
    float* T   = sm;                      // 32 * 1056
    float* Kt  = sm + TI * 1056;          // 128 * 68
    float* qs  = Kt + 128 * 68;           // 32 * 64
    float* ms  = qs + TI * DDIM;          // 1024
    float* tst = ms + SS;                 // 1056 (transposed tdsm)

    const int i0 = blockIdx.x * TI;
    const int h  = blockIdx.y;
    const int b  = blockIdx.z;
    const int tid = threadIdx.x, lane = tid & 31, w = tid >> 5;

    // ---- phase 0: q rows, mask, transposed tdsm ----
    {
        const float4* mq4 = (const float4*)mq;
#pragma unroll
        for (int l = 0; l < 2; l++) {
            int li = tid + 256 * l;
            int r = li >> 4, kq = li & 15;
            *(float4*)&qs[r * DDIM + kq * 4] =
                mq4[(size_t)(b * SS + i0 + r) * 96 + h * 16 + kq];
        }
        const int4* m4 = (const int4*)mask;
        int4 mm = m4[(size_t)(b * SS) / 4 + tid];
        ms[4 * tid + 0] = mm.x ? 1.f : 0.f;
        ms[4 * tid + 1] = mm.y ? 1.f : 0.f;
        ms[4 * tid + 2] = mm.z ? 1.f : 0.f;
        ms[4 * tid + 3] = mm.w ? 1.f : 0.f;
#pragma unroll
        for (int l = 0; l < 4; l++) {
            int j = tid + 256 * l;
            tst[(j >> 5) * 33 + (j & 31)] = tdsm[b * SS + j];
        }
    }
    __syncthreads();

    // ---- phase 1: masked scores into transposed T ----
    for (int jt = 0; jt < 8; jt++) {
        const int j0 = jt * 128;
#pragma unroll
        for (int l = 0; l < 8; l++) {
            int li = tid + 256 * l;
            int j = li >> 4, kq = li & 15;
            float4 v = ((const float4*)mk)[(size_t)(b * SS + j0 + j) * 96 + h * 16 + kq];
            *(float4*)&Kt[j * 68 + kq * 4] = v;
        }
        __syncthreads();
        float acc[4][4] = {};
#pragma unroll
        for (int k = 0; k < DDIM; k += 4) {
            float4 q[4];
#pragma unroll
            for (int rr = 0; rr < 4; rr++)
                q[rr] = *(const float4*)&qs[(4 * w + rr) * DDIM + k];
#pragma unroll
            for (int jj = 0; jj < 4; jj++) {
                float4 kv = *(const float4*)&Kt[(lane + 32 * jj) * 68 + k];
#pragma unroll
                for (int rr = 0; rr < 4; rr++)
                    acc[rr][jj] += q[rr].x * kv.x + q[rr].y * kv.y +
                                   q[rr].z * kv.z + q[rr].w * kv.w;
            }
        }
#pragma unroll
        for (int rr = 0; rr < 4; rr++)
#pragma unroll
            for (int jj = 0; jj < 4; jj++) {
                int j = j0 + lane + 32 * jj;
                float v = acc[rr][jj] * 0.125f;
                if (!(ms[j] > 0.f)) v = -1e8f;
                T[(4 * w + rr) * 1056 + (4 * jt + jj) * 33 + lane] = v;
            }
        __syncthreads();
    }

    // ---- phase 2: per-row softmax -> cumsum -> rescore -> softmax ----
    {
        float gm = gammas[h];
        float gamma = -((gm > 20.f) ? gm : log1pf(expf(gm)));
#pragma unroll 1
        for (int rr = 0; rr < 4; rr++) {
            const int r = 4 * w + rr;
            const int i = i0 + r;
            float* Trow = T + r * 1056 + lane * 33;
            float s[32], p[32];
#pragma unroll
            for (int t = 0; t < 32; t++) s[t] = Trow[t];
            // softmax #1
            float mx = s[0];
#pragma unroll
            for (int t = 1; t < 32; t++) mx = fmaxf(mx, s[t]);
#pragma unroll
            for (int o = 16; o; o >>= 1) mx = fmaxf(mx, __shfl_xor_sync(0xffffffffu, mx, o));
            float sum = 0.f;
#pragma unroll
            for (int t = 0; t < 32; t++) {
                p[t] = (s[t] > -1e7f) ? __expf(s[t] - mx) : 0.f;
                sum += p[t];
            }
#pragma unroll
            for (int o = 16; o; o >>= 1) sum += __shfl_xor_sync(0xffffffffu, sum, o);
            float inv = 1.f / sum;
            // cumsum: local prefix then warp scan of lane totals
            float run = 0.f;
#pragma unroll
            for (int t = 0; t < 32; t++) { run += p[t] * inv; p[t] = run; }
            float tot = run;
            float ex = tot;
#pragma unroll
            for (int d = 1; d < 32; d <<= 1) {
                float y = __shfl_up_sync(0xffffffffu, ex, d);
                if (lane >= d) ex += y;
            }
            float total = __shfl_sync(0xffffffffu, ex, 31);
            float excl = ex - tot;
            // rescore
#pragma unroll
            for (int t = 0; t < 32; t++) {
                if (s[t] > -1e7f) {
                    int j = lane * 32 + t;
                    float pos = fabsf((float)(j - i));
                    float rem = total - (excl + p[t]);
                    float ds = sqrtf(fmaxf(rem * pos, 0.f));
                    float te = fmaxf(__expf(ds * gamma), 1e-5f);
                    if (j < i) te -= tst[lane * 33 + t];
                    s[t] *= te;
                }
            }
            // softmax #2
            float mx2 = s[0];
#pragma unroll
            for (int t = 1; t < 32; t++) mx2 = fmaxf(mx2, s[t]);
#pragma unroll
            for (int o = 16; o; o >>= 1) mx2 = fmaxf(mx2, __shfl_xor_sync(0xffffffffu, mx2, o));
            float sum2 = 0.f;
#pragma unroll
            for (int t = 0; t < 32; t++) {
                p[t] = (s[t] > -1e7f) ? __expf(s[t] - mx2) : 0.f;
                sum2 += p[t];
            }
#pragma unroll
            for (int o = 16; o; o >>= 1) sum2 += __shfl_xor_sync(0xffffffffu, sum2, o);
            float inv2 = 1.f / sum2;
#pragma unroll
            for (int t = 0; t < 32; t++) Trow[t] = p[t] * inv2;
        }
    }
    __syncthreads();

    // ---- phase 3: ctx = probs @ V ----
    float a[4][2] = {};
    for (int jt = 0; jt < 8; jt++) {
        const int j0 = jt * 128;
#pragma unroll
        for (int l = 0; l < 8; l++) {
            int li = tid + 256 * l;
            int j = li >> 4, kq = li & 15;
            float4 v = ((const float4*)mv)[(size_t)(b * SS + j0 + j) * 96 + h * 16 + kq];
            *(float4*)&Kt[j * 68 + kq * 4] = v;
        }
        __syncthreads();
#pragma unroll 4
        for (int jl = 0; jl < 128; jl++) {
            int col = 4 * jt + (jl >> 5);
            int row = jl & 31;
            float v0 = Kt[jl * 68 + lane];
            float v1 = Kt[jl * 68 + 32 + lane];
#pragma unroll
            for (int rr = 0; rr < 4; rr++) {
                float pr = T[(4 * w + rr) * 1056 + col * 33 + row];
                a[rr][0] += pr * v0;
                a[rr][1] += pr * v1;
            }
        }
        __syncthreads();
    }
#pragma unroll
    for (int rr = 0; rr < 4; rr++) {
        size_t o = (size_t)(b * SS + i0 + 4 * w + rr) * 768 + h * DDIM;
        out[o + lane]      = a[rr][0];
        out[o + lane + 32] = a[rr][1];
    }
}

// ---------------- launch ----------------------------------------------------
extern "C" void kernel_launch(void* const* d_in, const int* in_sizes, int n_in,
                              void* d_out, int out_size) {
    const float* Q    = (const float*)d_in[0];
    const float* Kin  = (const float*)d_in[1];
    const float* V    = (const float*)d_in[2];
    const float* td   = (const float*)d_in[3];
    const int*   mask = (const int*)  d_in[4];
    const float* Wq   = (const float*)d_in[5];
    const float* Wk   = (const float*)d_in[6];
    const float* Wv   = (const float*)d_in[7];
    const float* dw_w = (const float*)d_in[8];
    const float* pw_w = (const float*)d_in[9];
    const float* sep_b= (const float*)d_in[10];
    const float* ck_W = (const float*)d_in[11];
    const float* ck_b = (const float*)d_in[12];
    const float* co_W = (const float*)d_in[13];
    const float* co_b = (const float*)d_in[14];
    const float* gammas=(const float*)d_in[15];
    float* out = (float*)d_out;

    float *mq, *mk, *mv, *co, *dw, *mkc, *ca, *ck, *tdsm;
    cudaGetSymbolAddress((void**)&mq,  g_mq);
    cudaGetSymbolAddress((void**)&mk,  g_mk);
    cudaGetSymbolAddress((void**)&mv,  g_mv);
    cudaGetSymbolAddress((void**)&co,  g_co);
    cudaGetSymbolAddress((void**)&dw,  g_dw);
    cudaGetSymbolAddress((void**)&mkc, g_mkc);
    cudaGetSymbolAddress((void**)&ca,  g_ca);
    cudaGetSymbolAddress((void**)&ck,  g_ck);
    cudaGetSymbolAddress((void**)&tdsm,g_tdsm);

    static int smem_set = 0;
    const int attn_smem = (TI * 1056 + 128 * 68 + TI * DDIM + SS + 1056) * 4;
    if (!smem_set) {
        cudaFuncSetAttribute(attn_kernel, cudaFuncAttributeMaxDynamicSharedMemorySize,
                             attn_smem);
        smem_set = 1;
    }

    // 4 independent projections in one batched launch
    Jobs4 j4;
    j4.A[0] = Q;   j4.B[0] = Wq;   j4.bias[0] = nullptr; j4.C[0] = mq;
    j4.A[1] = Kin; j4.B[1] = Wk;   j4.bias[1] = nullptr; j4.C[1] = mk;
    j4.A[2] = V;   j4.B[2] = Wv;   j4.bias[2] = nullptr; j4.C[2] = mv;
    j4.A[3] = V;   j4.B[3] = co_W; j4.bias[3] = co_b;    j4.C[3] = co;
    sgemm3<false><<<dim3(AHN / 128, NROWS / 128, 4), 256>>>(j4, NROWS, AHN, HIDN);

    dwconv_kernel<<<(NROWS * HIDN + 255) / 256, 256>>>(Kin, dw_w, dw);
    Jobs4 jp;
    jp.A[0] = dw; jp.B[0] = pw_w; jp.bias[0] = sep_b; jp.C[0] = mkc;
    jp.A[1] = jp.A[2] = jp.A[3] = nullptr;
    jp.B[1] = jp.B[2] = jp.B[3] = nullptr;
    jp.bias[1] = jp.bias[2] = jp.bias[3] = nullptr;
    jp.C[1] = jp.C[2] = jp.C[3] = nullptr;
    sgemm3<true><<<dim3(AHN / 128, NROWS / 128, 1), 256>>>(jp, NROWS, AHN, HIDN);

    emul_kernel<<<(NROWS * AHN + 255) / 256, 256>>>(mkc, mq, ca, NROWS * AHN);
    sgemm_small<false, true><<<dim3(1, NROWS / 64), 256>>>(ca, ck_W, ck_b, ck,
                                                           NROWS, NH * KSZ, AHN);
    ck_softmax_kernel<<<(NROWS * NH + 255) / 256, 256>>>(ck);
    conv_out_kernel<<<NROWS, AHN>>>(co, ck, out);

    tdsm_kernel<<<BB, 256>>>(td, mask, tdsm);
    attn_kernel<<<dim3(SS / TI, NH, BB), 256, attn_smem>>>(mq, mk, mv, mask, tdsm,
                                                           gammas, out);
}

// round 4
// speedup vs baseline: 1.8471x; 1.8471x over previous
#include <cuda_runtime.h>
#include <math.h>

#define BB   4
#define SS   1024
#define HIDN 768
#define AHN  384
#define NH   6
#define DDIM 64
#define KSZ  9
#define RPAD 4
#define NROWS (BB*SS)   /* 4096 */
#define TI   16         /* query rows per attention block */

// ---------------- scratch (static device globals: allocation-free) ----------
__device__ float g_mq [NROWS*AHN];
__device__ float g_mk [NROWS*AHN];
__device__ float g_mv [NROWS*AHN];
__device__ float g_co [NROWS*AHN];
__device__ float g_dw [NROWS*HIDN];
__device__ float g_mkc[NROWS*AHN];
__device__ float g_ca [NROWS*AHN];
__device__ float g_ck [NROWS*NH*KSZ];
__device__ float g_tdsm[BB*SS];

struct Jobs4 {
    const float* A[4];
    const float* B[4];
    const float* bias[4];
    float*       C[4];
};

// ---------------- batched SGEMM: 128x64 tile, 8x4 microtile (round-2 core) --
// BT=false: B stored (K,N).  BT=true: B stored (N,K).
// Requires M%128==0, N%64==0, K%16==0.
template<bool BT>
__global__ __launch_bounds__(256)
void sgemm2b(Jobs4 jobs, int M, int N, int K) {
    __shared__ float As[16 * 132];
    __shared__ float Bs[16 * 68];
    const float* __restrict__ A    = jobs.A[blockIdx.z];
    const float* __restrict__ Bm   = jobs.B[blockIdx.z];
    const float* __restrict__ bias = jobs.bias[blockIdx.z];
    float* __restrict__       C    = jobs.C[blockIdx.z];
    const int tid = threadIdx.x;
    const int tx = tid & 15, ty = tid >> 4;
    const int bm = blockIdx.y * 128, bn = blockIdx.x * 64;
    float acc[8][4] = {};
    for (int k0 = 0; k0 < K; k0 += 16) {
#pragma unroll
        for (int l = 0; l < 2; l++) {
            int li = tid + 256 * l;
            int m = li >> 2, kq = li & 3;
            float4 v = *(const float4*)&A[(size_t)(bm + m) * K + k0 + 4 * kq];
            As[(4 * kq + 0) * 132 + m] = v.x;
            As[(4 * kq + 1) * 132 + m] = v.y;
            As[(4 * kq + 2) * 132 + m] = v.z;
            As[(4 * kq + 3) * 132 + m] = v.w;
        }
        if (BT) {
            int n = tid >> 2, kq = tid & 3;
            float4 v = *(const float4*)&Bm[(size_t)(bn + n) * K + k0 + 4 * kq];
            Bs[(4 * kq + 0) * 68 + n] = v.x;
            Bs[(4 * kq + 1) * 68 + n] = v.y;
            Bs[(4 * kq + 2) * 68 + n] = v.z;
            Bs[(4 * kq + 3) * 68 + n] = v.w;
        } else {
            int k = tid >> 4, nq = tid & 15;
            float4 v = *(const float4*)&Bm[(size_t)(k0 + k) * N + bn + 4 * nq];
            *(float4*)&Bs[k * 68 + 4 * nq] = v;
        }
        __syncthreads();
#pragma unroll
        for (int k = 0; k < 16; k++) {
            float4 a0 = *(const float4*)&As[k * 132 + ty * 8];
            float4 a1 = *(const float4*)&As[k * 132 + ty * 8 + 4];
            float4 b0 = *(const float4*)&Bs[k * 68 + tx * 4];
            float av[8] = {a0.x, a0.y, a0.z, a0.w, a1.x, a1.y, a1.z, a1.w};
            float bv[4] = {b0.x, b0.y, b0.z, b0.w};
#pragma unroll
            for (int u = 0; u < 8; u++)
#pragma unroll
                for (int v = 0; v < 4; v++) acc[u][v] += av[u] * bv[v];
        }
        __syncthreads();
    }
    float4 bb = make_float4(0.f, 0.f, 0.f, 0.f);
    if (bias) bb = *(const float4*)&bias[bn + tx * 4];
#pragma unroll
    for (int u = 0; u < 8; u++) {
        float4 o;
        o.x = acc[u][0] + bb.x;
        o.y = acc[u][1] + bb.y;
        o.z = acc[u][2] + bb.z;
        o.w = acc[u][3] + bb.w;
        *(float4*)&C[(size_t)(bm + ty * 8 + u) * N + bn + tx * 4] = o;
    }
}

// ---------------- small guarded SGEMM (for N=54 conv-kernel layer) ----------
template<bool BT, bool BIAS>
__global__ void sgemm_small(const float* __restrict__ A, const float* __restrict__ Bm,
                            const float* __restrict__ bias, float* __restrict__ C,
                            int M, int N, int K) {
    __shared__ float As[16][64];
    __shared__ float Bs[16][64];
    const int tid = threadIdx.x;
    const int tx = tid & 15, ty = tid >> 4;
    const int bm = blockIdx.y * 64, bn = blockIdx.x * 64;
    float acc[4][4] = {};
    for (int k0 = 0; k0 < K; k0 += 16) {
#pragma unroll
        for (int l = 0; l < 4; l++) {
            int idx = tid + l * 256;
            int m = idx >> 4, k = idx & 15;
            As[k][m] = A[(size_t)(bm + m) * K + (k0 + k)];
        }
#pragma unroll
        for (int l = 0; l < 4; l++) {
            int idx = tid + l * 256;
            if (BT) {
                int n = idx >> 4, k = idx & 15;
                Bs[k][n] = (bn + n < N) ? Bm[(size_t)(bn + n) * K + (k0 + k)] : 0.f;
            } else {
                int k = idx >> 6, n = idx & 63;
                Bs[k][n] = (bn + n < N) ? Bm[(size_t)(k0 + k) * N + (bn + n)] : 0.f;
            }
        }
        __syncthreads();
#pragma unroll
        for (int k = 0; k < 16; k++) {
            float a[4], bv[4];
#pragma unroll
            for (int u = 0; u < 4; u++) a[u]  = As[k][ty * 4 + u];
#pragma unroll
            for (int v = 0; v < 4; v++) bv[v] = Bs[k][tx * 4 + v];
#pragma unroll
            for (int u = 0; u < 4; u++)
#pragma unroll
                for (int v = 0; v < 4; v++) acc[u][v] += a[u] * bv[v];
        }
        __syncthreads();
    }
#pragma unroll
    for (int u = 0; u < 4; u++) {
        int m = bm + ty * 4 + u;
#pragma unroll
        for (int v = 0; v < 4; v++) {
            int n = bn + tx * 4 + v;
            if (n < N) C[(size_t)m * N + n] = acc[u][v] + (BIAS ? bias[n] : 0.f);
        }
    }
}

// ---------------- depthwise conv over sequence (K input) --------------------
__global__ void dwconv_kernel(const float* __restrict__ Kin,
                              const float* __restrict__ dw_w,
                              float* __restrict__ out) {
    int e = blockIdx.x * 256 + threadIdx.x;
    if (e >= NROWS * HIDN) return;
    int c = e % HIDN;
    int bs = e / HIDN;
    int s = bs % SS, b = bs / SS;
    float acc = 0.f;
#pragma unroll
    for (int t = 0; t < KSZ; t++) {
        int sp = s + t - RPAD;
        if (sp >= 0 && sp < SS)
            acc += Kin[((size_t)b * SS + sp) * HIDN + c] * dw_w[c * KSZ + t];
    }
    out[e] = acc;
}

// ---------------- elementwise multiply --------------------------------------
__global__ void emul_kernel(const float* __restrict__ a, const float* __restrict__ b,
                            float* __restrict__ c, int n) {
    int i = blockIdx.x * 256 + threadIdx.x;
    if (i < n) c[i] = a[i] * b[i];
}

// ---------------- per (b,s,h) softmax over KS kernel taps --------------------
__global__ void ck_softmax_kernel(float* __restrict__ ck) {
    int r = blockIdx.x * 256 + threadIdx.x;
    if (r >= NROWS * NH) return;
    int row = r / NH, h = r % NH;
    float* p = ck + (size_t)row * (NH * KSZ) + h * KSZ;
    float mx = p[0];
#pragma unroll
    for (int t = 1; t < KSZ; t++) mx = fmaxf(mx, p[t]);
    float e[KSZ]; float s = 0.f;
#pragma unroll
    for (int t = 0; t < KSZ; t++) { e[t] = __expf(p[t] - mx); s += e[t]; }
    float inv = 1.f / s;
#pragma unroll
    for (int t = 0; t < KSZ; t++) p[t] = e[t] * inv;
}

// ---------------- dynamic-span conv output (second half of out) -------------
__global__ void conv_out_kernel(const float* __restrict__ co,
                                const float* __restrict__ ck,
                                float* __restrict__ out) {
    int r = blockIdx.x;          // (b*S+s)
    int t = threadIdx.x;         // 0..383 = h*64+d
    int h = t >> 6;
    int b = r / SS, s = r % SS;
    __shared__ float cks[NH * KSZ];
    if (t < NH * KSZ) cks[t] = ck[(size_t)r * (NH * KSZ) + t];
    __syncthreads();
    float acc = 0.f;
#pragma unroll
    for (int k = 0; k < KSZ; k++) {
        int sp = s + k - RPAD;
        if (sp >= 0 && sp < SS)
            acc += co[((size_t)b * SS + sp) * AHN + t] * cks[h * KSZ + k];
    }
    out[(size_t)r * 768 + AHN + t] = acc;
}

// ---------------- td softmax (key-mask only: independent of i,h) ------------
__global__ void tdsm_kernel(const float* __restrict__ td, const int* __restrict__ mask,
                            float* __restrict__ out) {
    int b = blockIdx.x;
    int tid = threadIdx.x, lane = tid & 31, wid = tid >> 5;
    __shared__ float buf[SS];
    __shared__ float red[8];
    float ss = 0.f;
    for (int j = tid; j < SS; j += 256) { float v = td[b * SS + j]; ss += v * v; }
#pragma unroll
    for (int o = 16; o > 0; o >>= 1) ss += __shfl_xor_sync(0xffffffffu, ss, o);
    if (lane == 0) red[wid] = ss;
    __syncthreads();
    float tot = 0.f;
#pragma unroll
    for (int w = 0; w < 8; w++) tot += red[w];
    float nrm = fmaxf(sqrtf(tot), 1e-12f);
    __syncthreads();
    float mx = -3.4e38f;
    for (int j = tid; j < SS; j += 256) {
        float v = mask[b * SS + j] ? td[b * SS + j] / nrm : -1e4f;
        buf[j] = v;
        mx = fmaxf(mx, v);
    }
#pragma unroll
    for (int o = 16; o > 0; o >>= 1) mx = fmaxf(mx, __shfl_xor_sync(0xffffffffu, mx, o));
    if (lane == 0) red[wid] = mx;
    __syncthreads();
    float bmx = red[0];
#pragma unroll
    for (int w = 1; w < 8; w++) bmx = fmaxf(bmx, red[w]);
    __syncthreads();
    float sum = 0.f;
    for (int j = tid; j < SS; j += 256) {
        float e = expf(buf[j] - bmx);
        buf[j] = e;
        sum += e;
    }
#pragma unroll
    for (int o = 16; o > 0; o >>= 1) sum += __shfl_xor_sync(0xffffffffu, sum, o);
    if (lane == 0) red[wid] = sum;
    __syncthreads();
    float bsum = 0.f;
#pragma unroll
    for (int w = 0; w < 8; w++) bsum += red[w];
    float inv = 1.f / bsum;
    __syncthreads();
    for (int j = tid; j < SS; j += 256) out[b * SS + j] = buf[j] * inv;
}

// ---------------- attention: 16 query rows per block ------------------------
// block = (i-tile, h, b); 256 threads = 8 warps; warp w owns rows 2w, 2w+1.
// Scores/probs stored TRANSPOSED: addr(j) = (j>>5)*33 + (j&31), so in phase 2
// each lane owns contiguous j = lane*32 .. lane*32+31 (conflict-free, fast scan).
__global__ __launch_bounds__(256)
void attn_kernel(const float* __restrict__ mq, const float* __restrict__ mk,
                 const float* __restrict__ mv, const int* __restrict__ mask,
                 const float* __restrict__ tdsm, const float* __restrict__ gammas,
                 float* __restrict__ out) {
    extern __shared__ float sm[];
    float* T   = sm;                      // 16 * 1056
    float* Kt  = sm + TI * 1056;          // 128 * 68
    float* qs  = Kt + 128 * 68;           // 16 * 64
    float* tst = qs + TI * DDIM;          // 1056 (transposed tdsm)

    const int i0 = blockIdx.x * TI;
    const int h  = blockIdx.y;
    const int b  = blockIdx.z;
    const int tid = threadIdx.x, lane = tid & 31, w = tid >> 5;

    // ---- phase 0: q rows + transposed tdsm ----
    {
        int r = tid >> 4, kq = tid & 15;
        const float4* mq4 = (const float4*)mq;
        *(float4*)&qs[r * DDIM + kq * 4] =
            mq4[(size_t)(b * SS + i0 + r) * 96 + h * 16 + kq];
#pragma unroll
        for (int l = 0; l < 4; l++) {
            int j = tid + 256 * l;
            tst[(j >> 5) * 33 + (j & 31)] = tdsm[b * SS + j];
        }
    }
    __syncthreads();

    // ---- phase 1: masked scores into transposed T ----
    const int rg = tid >> 5;
    for (int jt = 0; jt < 8; jt++) {
        const int j0 = jt * 128;
#pragma unroll
        for (int l = 0; l < 8; l++) {
            int li = tid + 256 * l;
            int j = li >> 4, kq = li & 15;
            float4 v = ((const float4*)mk)[(size_t)(b * SS + j0 + j) * 96 + h * 16 + kq];
            *(float4*)&Kt[j * 68 + kq * 4] = v;
        }
        __syncthreads();
        float acc[2][4] = {};
#pragma unroll
        for (int k = 0; k < DDIM; k += 4) {
            float4 q0 = *(const float4*)&qs[(2 * rg) * DDIM + k];
            float4 q1 = *(const float4*)&qs[(2 * rg + 1) * DDIM + k];
#pragma unroll
            for (int jj = 0; jj < 4; jj++) {
                float4 kv = *(const float4*)&Kt[(lane + 32 * jj) * 68 + k];
                acc[0][jj] += q0.x * kv.x + q0.y * kv.y + q0.z * kv.z + q0.w * kv.w;
                acc[1][jj] += q1.x * kv.x + q1.y * kv.y + q1.z * kv.z + q1.w * kv.w;
            }
        }
#pragma unroll
        for (int jj = 0; jj < 4; jj++) {
            int j = j0 + lane + 32 * jj;
            int mok = mask[b * SS + j];
#pragma unroll
            for (int rr = 0; rr < 2; rr++) {
                float v = acc[rr][jj] * 0.125f;
                if (!mok) v = -1e8f;
                T[(2 * rg + rr) * 1056 + (4 * jt + jj) * 33 + lane] = v;
            }
        }
        __syncthreads();
    }

    // ---- phase 2: per-row softmax -> cumsum -> rescore -> softmax ----
    {
        float gm = gammas[h];
        float gamma = -((gm > 20.f) ? gm : log1pf(expf(gm)));
#pragma unroll 1
        for (int rr = 0; rr < 2; rr++) {
            const int r = 2 * w + rr;
            const int i = i0 + r;
            float* Trow = T + r * 1056 + lane * 33;
            float s[32], p[32];
#pragma unroll
            for (int t = 0; t < 32; t++) s[t] = Trow[t];
            // softmax #1
            float mx = s[0];
#pragma unroll
            for (int t = 1; t < 32; t++) mx = fmaxf(mx, s[t]);
#pragma unroll
            for (int o = 16; o; o >>= 1) mx = fmaxf(mx, __shfl_xor_sync(0xffffffffu, mx, o));
            float sum = 0.f;
#pragma unroll
            for (int t = 0; t < 32; t++) {
                p[t] = (s[t] > -1e7f) ? __expf(s[t] - mx) : 0.f;
                sum += p[t];
            }
#pragma unroll
            for (int o = 16; o; o >>= 1) sum += __shfl_xor_sync(0xffffffffu, sum, o);
            float inv = 1.f / sum;
            // cumsum: local prefix then warp scan of lane totals
            float run = 0.f;
#pragma unroll
            for (int t = 0; t < 32; t++) { run += p[t] * inv; p[t] = run; }
            float tot = run;
            float ex = tot;
#pragma unroll
            for (int d = 1; d < 32; d <<= 1) {
                float y = __shfl_up_sync(0xffffffffu, ex, d);
                if (lane >= d) ex += y;
            }
            float total = __shfl_sync(0xffffffffu, ex, 31);
            float excl = ex - tot;
            // rescore with distance decay
#pragma unroll
            for (int t = 0; t < 32; t++) {
                if (s[t] > -1e7f) {
                    int j = lane * 32 + t;
                    float pos = fabsf((float)(j - i));
                    float rem = total - (excl + p[t]);
                    float ds = sqrtf(fmaxf(rem * pos, 0.f));
                    float te = fmaxf(__expf(ds * gamma), 1e-5f);
                    if (j < i) te -= tst[lane * 33 + t];
                    s[t] *= te;
                }
            }
            // softmax #2
            float mx2 = s[0];
#pragma unroll
            for (int t = 1; t < 32; t++) mx2 = fmaxf(mx2, s[t]);
#pragma unroll
            for (int o = 16; o; o >>= 1) mx2 = fmaxf(mx2, __shfl_xor_sync(0xffffffffu, mx2, o));
            float sum2 = 0.f;
#pragma unroll
            for (int t = 0; t < 32; t++) {
                p[t] = (s[t] > -1e7f) ? __expf(s[t] - mx2) : 0.f;
                sum2 += p[t];
            }
#pragma unroll
            for (int o = 16; o; o >>= 1) sum2 += __shfl_xor_sync(0xffffffffu, sum2, o);
            float inv2 = 1.f / sum2;
#pragma unroll
            for (int t = 0; t < 32; t++) Trow[t] = p[t] * inv2;
        }
    }
    __syncthreads();

    // ---- phase 3: ctx = probs @ V ----
    float a[2][2] = {};
    for (int jt = 0; jt < 8; jt++) {
        const int j0 = jt * 128;
#pragma unroll
        for (int l = 0; l < 8; l++) {
            int li = tid + 256 * l;
            int j = li >> 4, kq = li & 15;
            float4 v = ((const float4*)mv)[(size_t)(b * SS + j0 + j) * 96 + h * 16 + kq];
            *(float4*)&Kt[j * 68 + kq * 4] = v;
        }
        __syncthreads();
#pragma unroll 4
        for (int jl = 0; jl < 128; jl++) {
            int col = 4 * jt + (jl >> 5);
            int row = jl & 31;
            float v0 = Kt[jl * 68 + lane];
            float v1 = Kt[jl * 68 + 32 + lane];
#pragma unroll
            for (int rr = 0; rr < 2; rr++) {
                float pr = T[(2 * rg + rr) * 1056 + col * 33 + row];
                a[rr][0] += pr * v0;
                a[rr][1] += pr * v1;
            }
        }
        __syncthreads();
    }
#pragma unroll
    for (int rr = 0; rr < 2; rr++) {
        size_t o = (size_t)(b * SS + i0 + 2 * rg + rr) * 768 + h * DDIM;
        out[o + lane]      = a[rr][0];
        out[o + lane + 32] = a[rr][1];
    }
}

// ---------------- launch ----------------------------------------------------
extern "C" void kernel_launch(void* const* d_in, const int* in_sizes, int n_in,
                              void* d_out, int out_size) {
    const float* Q    = (const float*)d_in[0];
    const float* Kin  = (const float*)d_in[1];
    const float* V    = (const float*)d_in[2];
    const float* td   = (const float*)d_in[3];
    const int*   mask = (const int*)  d_in[4];
    const float* Wq   = (const float*)d_in[5];
    const float* Wk   = (const float*)d_in[6];
    const float* Wv   = (const float*)d_in[7];
    const float* dw_w = (const float*)d_in[8];
    const float* pw_w = (const float*)d_in[9];
    const float* sep_b= (const float*)d_in[10];
    const float* ck_W = (const float*)d_in[11];
    const float* ck_b = (const float*)d_in[12];
    const float* co_W = (const float*)d_in[13];
    const float* co_b = (const float*)d_in[14];
    const float* gammas=(const float*)d_in[15];
    float* out = (float*)d_out;

    float *mq, *mk, *mv, *co, *dw, *mkc, *ca, *ck, *tdsm;
    cudaGetSymbolAddress((void**)&mq,  g_mq);
    cudaGetSymbolAddress((void**)&mk,  g_mk);
    cudaGetSymbolAddress((void**)&mv,  g_mv);
    cudaGetSymbolAddress((void**)&co,  g_co);
    cudaGetSymbolAddress((void**)&dw,  g_dw);
    cudaGetSymbolAddress((void**)&mkc, g_mkc);
    cudaGetSymbolAddress((void**)&ca,  g_ca);
    cudaGetSymbolAddress((void**)&ck,  g_ck);
    cudaGetSymbolAddress((void**)&tdsm,g_tdsm);

    static int smem_set = 0;
    const int attn_smem = (TI * 1056 + 128 * 68 + TI * DDIM + 1056) * 4;  // 110720 B
    if (!smem_set) {
        cudaFuncSetAttribute(attn_kernel, cudaFuncAttributeMaxDynamicSharedMemorySize,
                             attn_smem);
        smem_set = 1;
    }

    // 4 independent projections in one batched launch
    Jobs4 j4;
    j4.A[0] = Q;   j4.B[0] = Wq;   j4.bias[0] = nullptr; j4.C[0] = mq;
    j4.A[1] = Kin; j4.B[1] = Wk;   j4.bias[1] = nullptr; j4.C[1] = mk;
    j4.A[2] = V;   j4.B[2] = Wv;   j4.bias[2] = nullptr; j4.C[2] = mv;
    j4.A[3] = V;   j4.B[3] = co_W; j4.bias[3] = co_b;    j4.C[3] = co;
    sgemm2b<false><<<dim3(AHN / 64, NROWS / 128, 4), 256>>>(j4, NROWS, AHN, HIDN);

    dwconv_kernel<<<(NROWS * HIDN + 255) / 256, 256>>>(Kin, dw_w, dw);
    Jobs4 jp;
    jp.A[0] = dw; jp.B[0] = pw_w; jp.bias[0] = sep_b; jp.C[0] = mkc;
    jp.A[1] = jp.A[2] = jp.A[3] = nullptr;
    jp.B[1] = jp.B[2] = jp.B[3] = nullptr;
    jp.bias[1] = jp.bias[2] = jp.bias[3] = nullptr;
    jp.C[1] = jp.C[2] = jp.C[3] = nullptr;
    sgemm2b<true><<<dim3(AHN / 64, NROWS / 128, 1), 256>>>(jp, NROWS, AHN, HIDN);

    emul_kernel<<<(NROWS * AHN + 255) / 256, 256>>>(mkc, mq, ca, NROWS * AHN);
    sgemm_small<false, true><<<dim3(1, NROWS / 64), 256>>>(ca, ck_W, ck_b, ck,
                                                           NROWS, NH * KSZ, AHN);
    ck_softmax_kernel<<<(NROWS * NH + 255) / 256, 256>>>(ck);
    conv_out_kernel<<<NROWS, AHN>>>(co, ck, out);

    tdsm_kernel<<<BB, 256>>>(td, mask, tdsm);
    attn_kernel<<<dim3(SS / TI, NH, BB), 256, attn_smem>>>(mq, mk, mv, mask, tdsm,
                                                           gammas, out);
}

// round 5
// speedup vs baseline: 2.5924x; 1.4035x over previous
#include <cuda_runtime.h>
#include <cuda_fp16.h>
#include <math.h>

#define BB   4
#define SS   1024
#define HIDN 768
#define AHN  384
#define NH   6
#define DDIM 64
#define KSZ  9
#define RPAD 4
#define NROWS (BB*SS)   /* 4096 */
#define TI   16         /* query rows per attention block */
#define HPITCH 40       /* smem half pitch for hgemm tiles */

// ---------------- scratch (static device globals: allocation-free) ----------
__device__ float g_mq [NROWS*AHN];
__device__ float g_mk [NROWS*AHN];
__device__ float g_mv [NROWS*AHN];
__device__ float g_co [NROWS*AHN];
__device__ float g_mkc[NROWS*AHN];
__device__ float g_ca [NROWS*AHN];
__device__ float g_ck [NROWS*NH*KSZ];
__device__ float g_tdsm[BB*SS];
// half-precision staging
__device__ __half g_Qh [NROWS*HIDN];
__device__ __half g_Kh [NROWS*HIDN];
__device__ __half g_Vh [NROWS*HIDN];
__device__ __half g_dwh[NROWS*HIDN];
__device__ __half g_WqT[AHN*HIDN];   // (N,K) layouts
__device__ __half g_WkT[AHN*HIDN];
__device__ __half g_WvT[AHN*HIDN];
__device__ __half g_coT[AHN*HIDN];
__device__ __half g_pwh[AHN*HIDN];   // pw_w already (N,K)

struct JobsH {
    const __half* A[5];
    const __half* B[5];   // (N, K) row-major half
    const float*  bias[5];
    float*        C[5];
};

// ---------------- fp32 -> fp16 convert ---------------------------------------
__global__ void convert_kernel(const float* __restrict__ in, __half* __restrict__ out,
                               int n4) {
    int i = blockIdx.x * 256 + threadIdx.x;
    if (i >= n4) return;
    float4 v = ((const float4*)in)[i];
    __half2* o = (__half2*)out;
    o[2 * i]     = __floats2half2_rn(v.x, v.y);
    o[2 * i + 1] = __floats2half2_rn(v.z, v.w);
}

// ---------------- transpose + convert: (R,C) fp32 -> (C,R) half --------------
__global__ void transconv_kernel(const float* __restrict__ in, __half* __restrict__ out,
                                 int R, int C) {
    __shared__ float t[32][33];
    int c0 = blockIdx.x * 32, r0 = blockIdx.y * 32;
    int tx = threadIdx.x, ty = threadIdx.y;
#pragma unroll
    for (int l = 0; l < 4; l++)
        t[ty + 8 * l][tx] = in[(size_t)(r0 + ty + 8 * l) * C + c0 + tx];
    __syncthreads();
#pragma unroll
    for (int l = 0; l < 4; l++)
        out[(size_t)(c0 + ty + 8 * l) * R + r0 + tx] =
            __float2half_rn(t[tx][ty + 8 * l]);
}

// ---------------- HGEMM: C fp32 = A(M,K)h x B'(N,K)h, 128x128 tile ----------
// mma.sync.m16n8k16 f32.f16.f16.f32; warp tile 64x32; double-buffered smem.
__global__ __launch_bounds__(256)
void hgemm(JobsH jobs, int M, int N, int K) {
    __shared__ __align__(16) __half Asm[2][128 * HPITCH];
    __shared__ __align__(16) __half Bsm[2][128 * HPITCH];
    const __half* __restrict__ A    = jobs.A[blockIdx.z];
    const __half* __restrict__ Bm   = jobs.B[blockIdx.z];
    const float*  __restrict__ bias = jobs.bias[blockIdx.z];
    float* __restrict__        C    = jobs.C[blockIdx.z];

    const int tid = threadIdx.x, lane = tid & 31, wid = tid >> 5;
    const int wm = wid >> 2, wn = wid & 3;          // 2x4 warp grid
    const int bm = blockIdx.y * 128, bn = blockIdx.x * 128;
    const int lrow = tid >> 1, lq = tid & 1;        // global-load mapping

    float D[4][4][4] = {};
    int4 pa[2], pb[2];

    const int nT = K / 32;
    // prologue: chunk 0
#pragma unroll
    for (int l = 0; l < 2; l++) {
        pa[l] = *(const int4*)&A[(size_t)(bm + lrow) * K + lq * 16 + l * 8];
        pb[l] = *(const int4*)&Bm[(size_t)(bn + lrow) * K + lq * 16 + l * 8];
    }
#pragma unroll
    for (int l = 0; l < 2; l++) {
        *(int4*)&Asm[0][lrow * HPITCH + lq * 16 + l * 8] = pa[l];
        *(int4*)&Bsm[0][lrow * HPITCH + lq * 16 + l * 8] = pb[l];
    }
    __syncthreads();

    const int r = lane >> 2, c2 = (lane & 3) * 2;

    for (int kt = 1; kt <= nT; kt++) {
        if (kt < nT) {
            const int k0 = kt * 32;
#pragma unroll
            for (int l = 0; l < 2; l++) {
                pa[l] = *(const int4*)&A[(size_t)(bm + lrow) * K + k0 + lq * 16 + l * 8];
                pb[l] = *(const int4*)&Bm[(size_t)(bn + lrow) * K + k0 + lq * 16 + l * 8];
            }
        }
        const int cb = (kt - 1) & 1;
#pragma unroll
        for (int kk = 0; kk < 32; kk += 16) {
            unsigned a[4][4], bfr[4][2];
#pragma unroll
            for (int mf = 0; mf < 4; mf++) {
                int row = wm * 64 + mf * 16 + r;
                int col = kk + c2;
                a[mf][0] = *(const unsigned*)&Asm[cb][row * HPITCH + col];
                a[mf][1] = *(const unsigned*)&Asm[cb][(row + 8) * HPITCH + col];
                a[mf][2] = *(const unsigned*)&Asm[cb][row * HPITCH + col + 8];
                a[mf][3] = *(const unsigned*)&Asm[cb][(row + 8) * HPITCH + col + 8];
            }
#pragma unroll
            for (int nf = 0; nf < 4; nf++) {
                int nr = wn * 32 + nf * 8 + r;
                bfr[nf][0] = *(const unsigned*)&Bsm[cb][nr * HPITCH + kk + c2];
                bfr[nf][1] = *(const unsigned*)&Bsm[cb][nr * HPITCH + kk + c2 + 8];
            }
#pragma unroll
            for (int mf = 0; mf < 4; mf++)
#pragma unroll
                for (int nf = 0; nf < 4; nf++) {
                    float* d = D[mf][nf];
                    asm volatile(
                        "mma.sync.aligned.m16n8k16.row.col.f32.f16.f16.f32 "
                        "{%0,%1,%2,%3}, {%4,%5,%6,%7}, {%8,%9}, {%0,%1,%2,%3};"
                        : "+f"(d[0]), "+f"(d[1]), "+f"(d[2]), "+f"(d[3])
                        : "r"(a[mf][0]), "r"(a[mf][1]), "r"(a[mf][2]), "r"(a[mf][3]),
                          "r"(bfr[nf][0]), "r"(bfr[nf][1]));
                }
        }
        if (kt < nT) {
            const int sb = kt & 1;
#pragma unroll
            for (int l = 0; l < 2; l++) {
                *(int4*)&Asm[sb][lrow * HPITCH + lq * 16 + l * 8] = pa[l];
                *(int4*)&Bsm[sb][lrow * HPITCH + lq * 16 + l * 8] = pb[l];
            }
            __syncthreads();
        }
    }

    // epilogue
#pragma unroll
    for (int mf = 0; mf < 4; mf++) {
        int row0 = bm + wm * 64 + mf * 16 + r;
#pragma unroll
        for (int nf = 0; nf < 4; nf++) {
            int coln = bn + wn * 32 + nf * 8 + c2;
            float bx = 0.f, by = 0.f;
            if (bias) { bx = bias[coln]; by = bias[coln + 1]; }
            float2 o0 = make_float2(D[mf][nf][0] + bx, D[mf][nf][1] + by);
            float2 o1 = make_float2(D[mf][nf][2] + bx, D[mf][nf][3] + by);
            *(float2*)&C[(size_t)row0 * N + coln]       = o0;
            *(float2*)&C[(size_t)(row0 + 8) * N + coln] = o1;
        }
    }
}

// ---------------- small guarded SGEMM (for N=54 conv-kernel layer) ----------
template<bool BT, bool BIAS>
__global__ void sgemm_small(const float* __restrict__ A, const float* __restrict__ Bm,
                            const float* __restrict__ bias, float* __restrict__ C,
                            int M, int N, int K) {
    __shared__ float As[16][64];
    __shared__ float Bs[16][64];
    const int tid = threadIdx.x;
    const int tx = tid & 15, ty = tid >> 4;
    const int bm = blockIdx.y * 64, bn = blockIdx.x * 64;
    float acc[4][4] = {};
    for (int k0 = 0; k0 < K; k0 += 16) {
#pragma unroll
        for (int l = 0; l < 4; l++) {
            int idx = tid + l * 256;
            int m = idx >> 4, k = idx & 15;
            As[k][m] = A[(size_t)(bm + m) * K + (k0 + k)];
        }
#pragma unroll
        for (int l = 0; l < 4; l++) {
            int idx = tid + l * 256;
            if (BT) {
                int n = idx >> 4, k = idx & 15;
                Bs[k][n] = (bn + n < N) ? Bm[(size_t)(bn + n) * K + (k0 + k)] : 0.f;
            } else {
                int k = idx >> 6, n = idx & 63;
                Bs[k][n] = (bn + n < N) ? Bm[(size_t)(k0 + k) * N + (bn + n)] : 0.f;
            }
        }
        __syncthreads();
#pragma unroll
        for (int k = 0; k < 16; k++) {
            float a[4], bv[4];
#pragma unroll
            for (int u = 0; u < 4; u++) a[u]  = As[k][ty * 4 + u];
#pragma unroll
            for (int v = 0; v < 4; v++) bv[v] = Bs[k][tx * 4 + v];
#pragma unroll
            for (int u = 0; u < 4; u++)
#pragma unroll
                for (int v = 0; v < 4; v++) acc[u][v] += a[u] * bv[v];
        }
        __syncthreads();
    }
#pragma unroll
    for (int u = 0; u < 4; u++) {
        int m = bm + ty * 4 + u;
#pragma unroll
        for (int v = 0; v < 4; v++) {
            int n = bn + tx * 4 + v;
            if (n < N) C[(size_t)m * N + n] = acc[u][v] + (BIAS ? bias[n] : 0.f);
        }
    }
}

// ---------------- depthwise conv over sequence (K input), half output -------
__global__ void dwconv_kernel(const float* __restrict__ Kin,
                              const float* __restrict__ dw_w,
                              __half* __restrict__ out) {
    int e = blockIdx.x * 256 + threadIdx.x;
    if (e >= NROWS * HIDN) return;
    int c = e % HIDN;
    int bs = e / HIDN;
    int s = bs % SS, b = bs / SS;
    float acc = 0.f;
#pragma unroll
    for (int t = 0; t < KSZ; t++) {
        int sp = s + t - RPAD;
        if (sp >= 0 && sp < SS)
            acc += Kin[((size_t)b * SS + sp) * HIDN + c] * dw_w[c * KSZ + t];
    }
    out[e] = __float2half_rn(acc);
}

// ---------------- elementwise multiply --------------------------------------
__global__ void emul_kernel(const float* __restrict__ a, const float* __restrict__ b,
                            float* __restrict__ c, int n) {
    int i = blockIdx.x * 256 + threadIdx.x;
    if (i < n) c[i] = a[i] * b[i];
}

// ---------------- per (b,s,h) softmax over KS kernel taps --------------------
__global__ void ck_softmax_kernel(float* __restrict__ ck) {
    int r = blockIdx.x * 256 + threadIdx.x;
    if (r >= NROWS * NH) return;
    int row = r / NH, h = r % NH;
    float* p = ck + (size_t)row * (NH * KSZ) + h * KSZ;
    float mx = p[0];
#pragma unroll
    for (int t = 1; t < KSZ; t++) mx = fmaxf(mx, p[t]);
    float e[KSZ]; float s = 0.f;
#pragma unroll
    for (int t = 0; t < KSZ; t++) { e[t] = __expf(p[t] - mx); s += e[t]; }
    float inv = 1.f / s;
#pragma unroll
    for (int t = 0; t < KSZ; t++) p[t] = e[t] * inv;
}

// ---------------- dynamic-span conv output (second half of out) -------------
__global__ void conv_out_kernel(const float* __restrict__ co,
                                const float* __restrict__ ck,
                                float* __restrict__ out) {
    int r = blockIdx.x;          // (b*S+s)
    int t = threadIdx.x;         // 0..383 = h*64+d
    int h = t >> 6;
    int b = r / SS, s = r % SS;
    __shared__ float cks[NH * KSZ];
    if (t < NH * KSZ) cks[t] = ck[(size_t)r * (NH * KSZ) + t];
    __syncthreads();
    float acc = 0.f;
#pragma unroll
    for (int k = 0; k < KSZ; k++) {
        int sp = s + k - RPAD;
        if (sp >= 0 && sp < SS)
            acc += co[((size_t)b * SS + sp) * AHN + t] * cks[h * KSZ + k];
    }
    out[(size_t)r * 768 + AHN + t] = acc;
}

// ---------------- td softmax (key-mask only: independent of i,h) ------------
__global__ void tdsm_kernel(const float* __restrict__ td, const int* __restrict__ mask,
                            float* __restrict__ out) {
    int b = blockIdx.x;
    int tid = threadIdx.x, lane = tid & 31, wid = tid >> 5;
    __shared__ float buf[SS];
    __shared__ float red[8];
    float ss = 0.f;
    for (int j = tid; j < SS; j += 256) { float v = td[b * SS + j]; ss += v * v; }
#pragma unroll
    for (int o = 16; o > 0; o >>= 1) ss += __shfl_xor_sync(0xffffffffu, ss, o);
    if (lane == 0) red[wid] = ss;
    __syncthreads();
    float tot = 0.f;
#pragma unroll
    for (int w = 0; w < 8; w++) tot += red[w];
    float nrm = fmaxf(sqrtf(tot), 1e-12f);
    __syncthreads();
    float mx = -3.4e38f;
    for (int j = tid; j < SS; j += 256) {
        float v = mask[b * SS + j] ? td[b * SS + j] / nrm : -1e4f;
        buf[j] = v;
        mx = fmaxf(mx, v);
    }
#pragma unroll
    for (int o = 16; o > 0; o >>= 1) mx = fmaxf(mx, __shfl_xor_sync(0xffffffffu, mx, o));
    if (lane == 0) red[wid] = mx;
    __syncthreads();
    float bmx = red[0];
#pragma unroll
    for (int w = 1; w < 8; w++) bmx = fmaxf(bmx, red[w]);
    __syncthreads();
    float sum = 0.f;
    for (int j = tid; j < SS; j += 256) {
        float e = expf(buf[j] - bmx);
        buf[j] = e;
        sum += e;
    }
#pragma unroll
    for (int o = 16; o > 0; o >>= 1) sum += __shfl_xor_sync(0xffffffffu, sum, o);
    if (lane == 0) red[wid] = sum;
    __syncthreads();
    float bsum = 0.f;
#pragma unroll
    for (int w = 0; w < 8; w++) bsum += red[w];
    float inv = 1.f / bsum;
    __syncthreads();
    for (int j = tid; j < SS; j += 256) out[b * SS + j] = buf[j] * inv;
}

// ---------------- attention: 16 query rows per block (unchanged) ------------
__global__ __launch_bounds__(256)
void attn_kernel(const float* __restrict__ mq, const float* __restrict__ mk,
                 const float* __restrict__ mv, const int* __restrict__ mask,
                 const float* __restrict__ tdsm, const float* __restrict__ gammas,
                 float* __restrict__ out) {
    extern __shared__ float sm[];
    float* T   = sm;                      // 16 * 1056
    float* Kt  = sm + TI * 1056;          // 128 * 68
    float* qs  = Kt + 128 * 68;           // 16 * 64
    float* tst = qs + TI * DDIM;          // 1056 (transposed tdsm)

    const int i0 = blockIdx.x * TI;
    const int h  = blockIdx.y;
    const int b  = blockIdx.z;
    const int tid = threadIdx.x, lane = tid & 31, w = tid >> 5;

    {
        int r = tid >> 4, kq = tid & 15;
        const float4* mq4 = (const float4*)mq;
        *(float4*)&qs[r * DDIM + kq * 4] =
            mq4[(size_t)(b * SS + i0 + r) * 96 + h * 16 + kq];
#pragma unroll
        for (int l = 0; l < 4; l++) {
            int j = tid + 256 * l;
            tst[(j >> 5) * 33 + (j & 31)] = tdsm[b * SS + j];
        }
    }
    __syncthreads();

    const int rg = tid >> 5;
    for (int jt = 0; jt < 8; jt++) {
        const int j0 = jt * 128;
#pragma unroll
        for (int l = 0; l < 8; l++) {
            int li = tid + 256 * l;
            int j = li >> 4, kq = li & 15;
            float4 v = ((const float4*)mk)[(size_t)(b * SS + j0 + j) * 96 + h * 16 + kq];
            *(float4*)&Kt[j * 68 + kq * 4] = v;
        }
        __syncthreads();
        float acc[2][4] = {};
#pragma unroll
        for (int k = 0; k < DDIM; k += 4) {
            float4 q0 = *(const float4*)&qs[(2 * rg) * DDIM + k];
            float4 q1 = *(const float4*)&qs[(2 * rg + 1) * DDIM + k];
#pragma unroll
            for (int jj = 0; jj < 4; jj++) {
                float4 kv = *(const float4*)&Kt[(lane + 32 * jj) * 68 + k];
                acc[0][jj] += q0.x * kv.x + q0.y * kv.y + q0.z * kv.z + q0.w * kv.w;
                acc[1][jj] += q1.x * kv.x + q1.y * kv.y + q1.z * kv.z + q1.w * kv.w;
            }
        }
#pragma unroll
        for (int jj = 0; jj < 4; jj++) {
            int j = j0 + lane + 32 * jj;
            int mok = mask[b * SS + j];
#pragma unroll
            for (int rr = 0; rr < 2; rr++) {
                float v = acc[rr][jj] * 0.125f;
                if (!mok) v = -1e8f;
                T[(2 * rg + rr) * 1056 + (4 * jt + jj) * 33 + lane] = v;
            }
        }
        __syncthreads();
    }

    {
        float gm = gammas[h];
        float gamma = -((gm > 20.f) ? gm : log1pf(expf(gm)));
#pragma unroll 1
        for (int rr = 0; rr < 2; rr++) {
            const int r = 2 * w + rr;
            const int i = i0 + r;
            float* Trow = T + r * 1056 + lane * 33;
            float s[32], p[32];
#pragma unroll
            for (int t = 0; t < 32; t++) s[t] = Trow[t];
            float mx = s[0];
#pragma unroll
            for (int t = 1; t < 32; t++) mx = fmaxf(mx, s[t]);
#pragma unroll
            for (int o = 16; o; o >>= 1) mx = fmaxf(mx, __shfl_xor_sync(0xffffffffu, mx, o));
            float sum = 0.f;
#pragma unroll
            for (int t = 0; t < 32; t++) {
                p[t] = (s[t] > -1e7f) ? __expf(s[t] - mx) : 0.f;
                sum += p[t];
            }
#pragma unroll
            for (int o = 16; o; o >>= 1) sum += __shfl_xor_sync(0xffffffffu, sum, o);
            float inv = 1.f / sum;
            float run = 0.f;
#pragma unroll
            for (int t = 0; t < 32; t++) { run += p[t] * inv; p[t] = run; }
            float tot = run;
            float ex = tot;
#pragma unroll
            for (int d = 1; d < 32; d <<= 1) {
                float y = __shfl_up_sync(0xffffffffu, ex, d);
                if (lane >= d) ex += y;
            }
            float total = __shfl_sync(0xffffffffu, ex, 31);
            float excl = ex - tot;
#pragma unroll
            for (int t = 0; t < 32; t++) {
                if (s[t] > -1e7f) {
                    int j = lane * 32 + t;
                    float pos = fabsf((float)(j - i));
                    float rem = total - (excl + p[t]);
                    float ds = sqrtf(fmaxf(rem * pos, 0.f));
                    float te = fmaxf(__expf(ds * gamma), 1e-5f);
                    if (j < i) te -= tst[lane * 33 + t];
                    s[t] *= te;
                }
            }
            float mx2 = s[0];
#pragma unroll
            for (int t = 1; t < 32; t++) mx2 = fmaxf(mx2, s[t]);
#pragma unroll
            for (int o = 16; o; o >>= 1) mx2 = fmaxf(mx2, __shfl_xor_sync(0xffffffffu, mx2, o));
            float sum2 = 0.f;
#pragma unroll
            for (int t = 0; t < 32; t++) {
                p[t] = (s[t] > -1e7f) ? __expf(s[t] - mx2) : 0.f;
                sum2 += p[t];
            }
#pragma unroll
            for (int o = 16; o; o >>= 1) sum2 += __shfl_xor_sync(0xffffffffu, sum2, o);
            float inv2 = 1.f / sum2;
#pragma unroll
            for (int t = 0; t < 32; t++) Trow[t] = p[t] * inv2;
        }
    }
    __syncthreads();

    float a[2][2] = {};
    for (int jt = 0; jt < 8; jt++) {
        const int j0 = jt * 128;
#pragma unroll
        for (int l = 0; l < 8; l++) {
            int li = tid + 256 * l;
            int j = li >> 4, kq = li & 15;
            float4 v = ((const float4*)mv)[(size_t)(b * SS + j0 + j) * 96 + h * 16 + kq];
            *(float4*)&Kt[j * 68 + kq * 4] = v;
        }
        __syncthreads();
#pragma unroll 4
        for (int jl = 0; jl < 128; jl++) {
            int col = 4 * jt + (jl >> 5);
            int row = jl & 31;
            float v0 = Kt[jl * 68 + lane];
            float v1 = Kt[jl * 68 + 32 + lane];
#pragma unroll
            for (int rr = 0; rr < 2; rr++) {
                float pr = T[(2 * rg + rr) * 1056 + col * 33 + row];
                a[rr][0] += pr * v0;
                a[rr][1] += pr * v1;
            }
        }
        __syncthreads();
    }
#pragma unroll
    for (int rr = 0; rr < 2; rr++) {
        size_t o = (size_t)(b * SS + i0 + 2 * rg + rr) * 768 + h * DDIM;
        out[o + lane]      = a[rr][0];
        out[o + lane + 32] = a[rr][1];
    }
}

// ---------------- launch ----------------------------------------------------
extern "C" void kernel_launch(void* const* d_in, const int* in_sizes, int n_in,
                              void* d_out, int out_size) {
    const float* Q    = (const float*)d_in[0];
    const float* Kin  = (const float*)d_in[1];
    const float* V    = (const float*)d_in[2];
    const float* td   = (const float*)d_in[3];
    const int*   mask = (const int*)  d_in[4];
    const float* Wq   = (const float*)d_in[5];
    const float* Wk   = (const float*)d_in[6];
    const float* Wv   = (const float*)d_in[7];
    const float* dw_w = (const float*)d_in[8];
    const float* pw_w = (const float*)d_in[9];
    const float* sep_b= (const float*)d_in[10];
    const float* ck_W = (const float*)d_in[11];
    const float* ck_b = (const float*)d_in[12];
    const float* co_W = (const float*)d_in[13];
    const float* co_b = (const float*)d_in[14];
    const float* gammas=(const float*)d_in[15];
    float* out = (float*)d_out;

    float *mq, *mk, *mv, *co, *mkc, *ca, *ck, *tdsm;
    __half *Qh, *Kh, *Vh, *dwh, *WqT, *WkT, *WvT, *coT, *pwh;
    cudaGetSymbolAddress((void**)&mq,  g_mq);
    cudaGetSymbolAddress((void**)&mk,  g_mk);
    cudaGetSymbolAddress((void**)&mv,  g_mv);
    cudaGetSymbolAddress((void**)&co,  g_co);
    cudaGetSymbolAddress((void**)&mkc, g_mkc);
    cudaGetSymbolAddress((void**)&ca,  g_ca);
    cudaGetSymbolAddress((void**)&ck,  g_ck);
    cudaGetSymbolAddress((void**)&tdsm,g_tdsm);
    cudaGetSymbolAddress((void**)&Qh,  g_Qh);
    cudaGetSymbolAddress((void**)&Kh,  g_Kh);
    cudaGetSymbolAddress((void**)&Vh,  g_Vh);
    cudaGetSymbolAddress((void**)&dwh, g_dwh);
    cudaGetSymbolAddress((void**)&WqT, g_WqT);
    cudaGetSymbolAddress((void**)&WkT, g_WkT);
    cudaGetSymbolAddress((void**)&WvT, g_WvT);
    cudaGetSymbolAddress((void**)&coT, g_coT);
    cudaGetSymbolAddress((void**)&pwh, g_pwh);

    static int smem_set = 0;
    const int attn_smem = (TI * 1056 + 128 * 68 + TI * DDIM + 1056) * 4;  // 110720 B
    if (!smem_set) {
        cudaFuncSetAttribute(attn_kernel, cudaFuncAttributeMaxDynamicSharedMemorySize,
                             attn_smem);
        smem_set = 1;
    }

    // ---- pack: fp32 -> fp16 (activations + weights) ----
    const int nQKV4 = NROWS * HIDN / 4;
    convert_kernel<<<(nQKV4 + 255) / 256, 256>>>(Q,   Qh, nQKV4);
    convert_kernel<<<(nQKV4 + 255) / 256, 256>>>(Kin, Kh, nQKV4);
    convert_kernel<<<(nQKV4 + 255) / 256, 256>>>(V,   Vh, nQKV4);
    const int nW4 = AHN * HIDN / 4;
    convert_kernel<<<(nW4 + 255) / 256, 256>>>(pw_w, pwh, nW4);
    dim3 tB(32, 8), tG(AHN / 32, HIDN / 32);
    transconv_kernel<<<tG, tB>>>(Wq,   WqT, HIDN, AHN);
    transconv_kernel<<<tG, tB>>>(Wk,   WkT, HIDN, AHN);
    transconv_kernel<<<tG, tB>>>(Wv,   WvT, HIDN, AHN);
    transconv_kernel<<<tG, tB>>>(co_W, coT, HIDN, AHN);

    dwconv_kernel<<<(NROWS * HIDN + 255) / 256, 256>>>(Kin, dw_w, dwh);

    // ---- all 5 big GEMMs in one tensor-core launch ----
    JobsH jh;
    jh.A[0] = Qh;  jh.B[0] = WqT; jh.bias[0] = nullptr; jh.C[0] = mq;
    jh.A[1] = Kh;  jh.B[1] = WkT; jh.bias[1] = nullptr; jh.C[1] = mk;
    jh.A[2] = Vh;  jh.B[2] = WvT; jh.bias[2] = nullptr; jh.C[2] = mv;
    jh.A[3] = Vh;  jh.B[3] = coT; jh.bias[3] = co_b;    jh.C[3] = co;
    jh.A[4] = dwh; jh.B[4] = pwh; jh.bias[4] = sep_b;   jh.C[4] = mkc;
    hgemm<<<dim3(AHN / 128, NROWS / 128, 5), 256>>>(jh, NROWS, AHN, HIDN);

    emul_kernel<<<(NROWS * AHN + 255) / 256, 256>>>(mkc, mq, ca, NROWS * AHN);
    sgemm_small<false, true><<<dim3(1, NROWS / 64), 256>>>(ca, ck_W, ck_b, ck,
                                                           NROWS, NH * KSZ, AHN);
    ck_softmax_kernel<<<(NROWS * NH + 255) / 256, 256>>>(ck);
    conv_out_kernel<<<NROWS, AHN>>>(co, ck, out);

    tdsm_kernel<<<BB, 256>>>(td, mask, tdsm);
    attn_kernel<<<dim3(SS / TI, NH, BB), 256, attn_smem>>>(mq, mk, mv, mask, tdsm,
                                                           gammas, out);
}

// round 6
// speedup vs baseline: 4.3518x; 1.6787x over previous
#include <cuda_runtime.h>
#include <cuda_fp16.h>
#include <math.h>

#define BB   4
#define SS   1024
#define HIDN 768
#define AHN  384
#define NH   6
#define DDIM 64
#define KSZ  9
#define RPAD 4
#define NROWS (BB*SS)   /* 4096 */
#define TI   16         /* query rows per attention block */
#define HPITCH 40       /* smem half pitch for hgemm tiles */
#define TP   1064       /* attn score-row pitch (floats) */

// ---------------- scratch (static device globals: allocation-free) ----------
__device__ float g_mq [NROWS*AHN];
__device__ float g_co [NROWS*AHN];
__device__ float g_mkc[NROWS*AHN];
__device__ float g_ca [NROWS*AHN];
__device__ float g_ck [NROWS*NH*KSZ];
__device__ float g_tdsm[BB*SS];
// half-precision staging
__device__ __half g_Qh [NROWS*HIDN];
__device__ __half g_Kh [NROWS*HIDN];
__device__ __half g_Vh [NROWS*HIDN];
__device__ __half g_dwh[NROWS*HIDN];
__device__ __half g_WqT[AHN*HIDN];   // (N,K) layouts
__device__ __half g_WkT[AHN*HIDN];
__device__ __half g_WvT[AHN*HIDN];
__device__ __half g_coT[AHN*HIDN];
__device__ __half g_pwh[AHN*HIDN];
// half projection outputs for attention
__device__ __half g_mqh[NROWS*AHN];
__device__ __half g_mkh[NROWS*AHN];
__device__ __half g_mvh[NROWS*AHN];

struct JobsH {
    const __half* A[5];
    const __half* B[5];   // (N, K) row-major half
    const float*  bias[5];
    float*        C[5];   // fp32 out (may be null)
    __half*       Ch[5];  // half out (may be null)
};

// ---------------- fp32 -> fp16 convert ---------------------------------------
__global__ void convert_kernel(const float* __restrict__ in, __half* __restrict__ out,
                               int n4) {
    int i = blockIdx.x * 256 + threadIdx.x;
    if (i >= n4) return;
    float4 v = ((const float4*)in)[i];
    __half2* o = (__half2*)out;
    o[2 * i]     = __floats2half2_rn(v.x, v.y);
    o[2 * i + 1] = __floats2half2_rn(v.z, v.w);
}

// ---------------- transpose + convert: (R,C) fp32 -> (C,R) half --------------
__global__ void transconv_kernel(const float* __restrict__ in, __half* __restrict__ out,
                                 int R, int C) {
    __shared__ float t[32][33];
    int c0 = blockIdx.x * 32, r0 = blockIdx.y * 32;
    int tx = threadIdx.x, ty = threadIdx.y;
#pragma unroll
    for (int l = 0; l < 4; l++)
        t[ty + 8 * l][tx] = in[(size_t)(r0 + ty + 8 * l) * C + c0 + tx];
    __syncthreads();
#pragma unroll
    for (int l = 0; l < 4; l++)
        out[(size_t)(c0 + ty + 8 * l) * R + r0 + tx] =
            __float2half_rn(t[tx][ty + 8 * l]);
}

// ---------------- HGEMM: C = A(M,K)h x B'(N,K)h, 128x128 tile ---------------
__global__ __launch_bounds__(256)
void hgemm(JobsH jobs, int M, int N, int K) {
    __shared__ __align__(16) __half Asm[2][128 * HPITCH];
    __shared__ __align__(16) __half Bsm[2][128 * HPITCH];
    const __half* __restrict__ A    = jobs.A[blockIdx.z];
    const __half* __restrict__ Bm   = jobs.B[blockIdx.z];
    const float*  __restrict__ bias = jobs.bias[blockIdx.z];
    float* __restrict__        C    = jobs.C[blockIdx.z];
    __half* __restrict__       Ch   = jobs.Ch[blockIdx.z];

    const int tid = threadIdx.x, lane = tid & 31, wid = tid >> 5;
    const int wm = wid >> 2, wn = wid & 3;
    const int bm = blockIdx.y * 128, bn = blockIdx.x * 128;
    const int lrow = tid >> 1, lq = tid & 1;

    float D[4][4][4] = {};
    int4 pa[2], pb[2];
    const int nT = K / 32;

#pragma unroll
    for (int l = 0; l < 2; l++) {
        pa[l] = *(const int4*)&A[(size_t)(bm + lrow) * K + lq * 16 + l * 8];
        pb[l] = *(const int4*)&Bm[(size_t)(bn + lrow) * K + lq * 16 + l * 8];
    }
#pragma unroll
    for (int l = 0; l < 2; l++) {
        *(int4*)&Asm[0][lrow * HPITCH + lq * 16 + l * 8] = pa[l];
        *(int4*)&Bsm[0][lrow * HPITCH + lq * 16 + l * 8] = pb[l];
    }
    __syncthreads();

    const int r = lane >> 2, c2 = (lane & 3) * 2;

    for (int kt = 1; kt <= nT; kt++) {
        if (kt < nT) {
            const int k0 = kt * 32;
#pragma unroll
            for (int l = 0; l < 2; l++) {
                pa[l] = *(const int4*)&A[(size_t)(bm + lrow) * K + k0 + lq * 16 + l * 8];
                pb[l] = *(const int4*)&Bm[(size_t)(bn + lrow) * K + k0 + lq * 16 + l * 8];
            }
        }
        const int cb = (kt - 1) & 1;
#pragma unroll
        for (int kk = 0; kk < 32; kk += 16) {
            unsigned a[4][4], bfr[4][2];
#pragma unroll
            for (int mf = 0; mf < 4; mf++) {
                int row = wm * 64 + mf * 16 + r;
                int col = kk + c2;
                a[mf][0] = *(const unsigned*)&Asm[cb][row * HPITCH + col];
                a[mf][1] = *(const unsigned*)&Asm[cb][(row + 8) * HPITCH + col];
                a[mf][2] = *(const unsigned*)&Asm[cb][row * HPITCH + col + 8];
                a[mf][3] = *(const unsigned*)&Asm[cb][(row + 8) * HPITCH + col + 8];
            }
#pragma unroll
            for (int nf = 0; nf < 4; nf++) {
                int nr = wn * 32 + nf * 8 + r;
                bfr[nf][0] = *(const unsigned*)&Bsm[cb][nr * HPITCH + kk + c2];
                bfr[nf][1] = *(const unsigned*)&Bsm[cb][nr * HPITCH + kk + c2 + 8];
            }
#pragma unroll
            for (int mf = 0; mf < 4; mf++)
#pragma unroll
                for (int nf = 0; nf < 4; nf++) {
                    float* d = D[mf][nf];
                    asm volatile(
                        "mma.sync.aligned.m16n8k16.row.col.f32.f16.f16.f32 "
                        "{%0,%1,%2,%3}, {%4,%5,%6,%7}, {%8,%9}, {%0,%1,%2,%3};"
                        : "+f"(d[0]), "+f"(d[1]), "+f"(d[2]), "+f"(d[3])
                        : "r"(a[mf][0]), "r"(a[mf][1]), "r"(a[mf][2]), "r"(a[mf][3]),
                          "r"(bfr[nf][0]), "r"(bfr[nf][1]));
                }
        }
        if (kt < nT) {
            const int sb = kt & 1;
#pragma unroll
            for (int l = 0; l < 2; l++) {
                *(int4*)&Asm[sb][lrow * HPITCH + lq * 16 + l * 8] = pa[l];
                *(int4*)&Bsm[sb][lrow * HPITCH + lq * 16 + l * 8] = pb[l];
            }
            __syncthreads();
        }
    }

#pragma unroll
    for (int mf = 0; mf < 4; mf++) {
        int row0 = bm + wm * 64 + mf * 16 + r;
#pragma unroll
        for (int nf = 0; nf < 4; nf++) {
            int coln = bn + wn * 32 + nf * 8 + c2;
            float bx = 0.f, by = 0.f;
            if (bias) { bx = bias[coln]; by = bias[coln + 1]; }
            float v0 = D[mf][nf][0] + bx, v1 = D[mf][nf][1] + by;
            float v2 = D[mf][nf][2] + bx, v3 = D[mf][nf][3] + by;
            if (C) {
                *(float2*)&C[(size_t)row0 * N + coln]       = make_float2(v0, v1);
                *(float2*)&C[(size_t)(row0 + 8) * N + coln] = make_float2(v2, v3);
            }
            if (Ch) {
                *(__half2*)&Ch[(size_t)row0 * N + coln]       = __floats2half2_rn(v0, v1);
                *(__half2*)&Ch[(size_t)(row0 + 8) * N + coln] = __floats2half2_rn(v2, v3);
            }
        }
    }
}

// ---------------- small guarded SGEMM (for N=54 conv-kernel layer) ----------
template<bool BT, bool BIAS>
__global__ void sgemm_small(const float* __restrict__ A, const float* __restrict__ Bm,
                            const float* __restrict__ bias, float* __restrict__ C,
                            int M, int N, int K) {
    __shared__ float As[16][64];
    __shared__ float Bs[16][64];
    const int tid = threadIdx.x;
    const int tx = tid & 15, ty = tid >> 4;
    const int bm = blockIdx.y * 64, bn = blockIdx.x * 64;
    float acc[4][4] = {};
    for (int k0 = 0; k0 < K; k0 += 16) {
#pragma unroll
        for (int l = 0; l < 4; l++) {
            int idx = tid + l * 256;
            int m = idx >> 4, k = idx & 15;
            As[k][m] = A[(size_t)(bm + m) * K + (k0 + k)];
        }
#pragma unroll
        for (int l = 0; l < 4; l++) {
            int idx = tid + l * 256;
            if (BT) {
                int n = idx >> 4, k = idx & 15;
                Bs[k][n] = (bn + n < N) ? Bm[(size_t)(bn + n) * K + (k0 + k)] : 0.f;
            } else {
                int k = idx >> 6, n = idx & 63;
                Bs[k][n] = (bn + n < N) ? Bm[(size_t)(k0 + k) * N + (bn + n)] : 0.f;
            }
        }
        __syncthreads();
#pragma unroll
        for (int k = 0; k < 16; k++) {
            float a[4], bv[4];
#pragma unroll
            for (int u = 0; u < 4; u++) a[u]  = As[k][ty * 4 + u];
#pragma unroll
            for (int v = 0; v < 4; v++) bv[v] = Bs[k][tx * 4 + v];
#pragma unroll
            for (int u = 0; u < 4; u++)
#pragma unroll
                for (int v = 0; v < 4; v++) acc[u][v] += a[u] * bv[v];
        }
        __syncthreads();
    }
#pragma unroll
    for (int u = 0; u < 4; u++) {
        int m = bm + ty * 4 + u;
#pragma unroll
        for (int v = 0; v < 4; v++) {
            int n = bn + tx * 4 + v;
            if (n < N) C[(size_t)m * N + n] = acc[u][v] + (BIAS ? bias[n] : 0.f);
        }
    }
}

// ---------------- depthwise conv over sequence (K input), half output -------
__global__ void dwconv_kernel(const float* __restrict__ Kin,
                              const float* __restrict__ dw_w,
                              __half* __restrict__ out) {
    int e = blockIdx.x * 256 + threadIdx.x;
    if (e >= NROWS * HIDN) return;
    int c = e % HIDN;
    int bs = e / HIDN;
    int s = bs % SS, b = bs / SS;
    float acc = 0.f;
#pragma unroll
    for (int t = 0; t < KSZ; t++) {
        int sp = s + t - RPAD;
        if (sp >= 0 && sp < SS)
            acc += Kin[((size_t)b * SS + sp) * HIDN + c] * dw_w[c * KSZ + t];
    }
    out[e] = __float2half_rn(acc);
}

// ---------------- elementwise multiply --------------------------------------
__global__ void emul_kernel(const float* __restrict__ a, const float* __restrict__ b,
                            float* __restrict__ c, int n) {
    int i = blockIdx.x * 256 + threadIdx.x;
    if (i < n) c[i] = a[i] * b[i];
}

// ---------------- per (b,s,h) softmax over KS kernel taps --------------------
__global__ void ck_softmax_kernel(float* __restrict__ ck) {
    int r = blockIdx.x * 256 + threadIdx.x;
    if (r >= NROWS * NH) return;
    int row = r / NH, h = r % NH;
    float* p = ck + (size_t)row * (NH * KSZ) + h * KSZ;
    float mx = p[0];
#pragma unroll
    for (int t = 1; t < KSZ; t++) mx = fmaxf(mx, p[t]);
    float e[KSZ]; float s = 0.f;
#pragma unroll
    for (int t = 0; t < KSZ; t++) { e[t] = __expf(p[t] - mx); s += e[t]; }
    float inv = 1.f / s;
#pragma unroll
    for (int t = 0; t < KSZ; t++) p[t] = e[t] * inv;
}

// ---------------- dynamic-span conv output (second half of out) -------------
__global__ void conv_out_kernel(const float* __restrict__ co,
                                const float* __restrict__ ck,
                                float* __restrict__ out) {
    int r = blockIdx.x;
    int t = threadIdx.x;
    int h = t >> 6;
    int b = r / SS, s = r % SS;
    __shared__ float cks[NH * KSZ];
    if (t < NH * KSZ) cks[t] = ck[(size_t)r * (NH * KSZ) + t];
    __syncthreads();
    float acc = 0.f;
#pragma unroll
    for (int k = 0; k < KSZ; k++) {
        int sp = s + k - RPAD;
        if (sp >= 0 && sp < SS)
            acc += co[((size_t)b * SS + sp) * AHN + t] * cks[h * KSZ + k];
    }
    out[(size_t)r * 768 + AHN + t] = acc;
}

// ---------------- td softmax (key-mask only) --------------------------------
__global__ void tdsm_kernel(const float* __restrict__ td, const int* __restrict__ mask,
                            float* __restrict__ out) {
    int b = blockIdx.x;
    int tid = threadIdx.x, lane = tid & 31, wid = tid >> 5;
    __shared__ float buf[SS];
    __shared__ float red[8];
    float ss = 0.f;
    for (int j = tid; j < SS; j += 256) { float v = td[b * SS + j]; ss += v * v; }
#pragma unroll
    for (int o = 16; o > 0; o >>= 1) ss += __shfl_xor_sync(0xffffffffu, ss, o);
    if (lane == 0) red[wid] = ss;
    __syncthreads();
    float tot = 0.f;
#pragma unroll
    for (int w = 0; w < 8; w++) tot += red[w];
    float nrm = fmaxf(sqrtf(tot), 1e-12f);
    __syncthreads();
    float mx = -3.4e38f;
    for (int j = tid; j < SS; j += 256) {
        float v = mask[b * SS + j] ? td[b * SS + j] / nrm : -1e4f;
        buf[j] = v;
        mx = fmaxf(mx, v);
    }
#pragma unroll
    for (int o = 16; o > 0; o >>= 1) mx = fmaxf(mx, __shfl_xor_sync(0xffffffffu, mx, o));
    if (lane == 0) red[wid] = mx;
    __syncthreads();
    float bmx = red[0];
#pragma unroll
    for (int w = 1; w < 8; w++) bmx = fmaxf(bmx, red[w]);
    __syncthreads();
    float sum = 0.f;
    for (int j = tid; j < SS; j += 256) {
        float e = expf(buf[j] - bmx);
        buf[j] = e;
        sum += e;
    }
#pragma unroll
    for (int o = 16; o > 0; o >>= 1) sum += __shfl_xor_sync(0xffffffffu, sum, o);
    if (lane == 0) red[wid] = sum;
    __syncthreads();
    float bsum = 0.f;
#pragma unroll
    for (int w = 0; w < 8; w++) bsum += red[w];
    float inv = 1.f / bsum;
    __syncthreads();
    for (int j = tid; j < SS; j += 256) out[b * SS + j] = buf[j] * inv;
}

// ---------------- attention: 16 rows/block, tensor-core QK^T and PV ---------
// smem: T fp32 16xTP (scores for scan; per-row aliased half probs Ph)
//       KV: Ks (128x72 h) phase1 / Vts (64x138 h, transposed) phase3
__global__ __launch_bounds__(256)
void attn_kernel(const __half* __restrict__ mqh, const __half* __restrict__ mkh,
                 const __half* __restrict__ mvh, const int* __restrict__ mask,
                 const float* __restrict__ tdsm, const float* __restrict__ gammas,
                 float* __restrict__ out) {
    extern __shared__ float sm[];
    float* T   = sm;                       // 16*TP floats
    float* KV  = T + TI * TP;              // 4608 floats (18432 B)
    float* qsf = KV + 4608;                // 576 floats (Qs halves)
    float* tst = qsf + 576;                // 1056
    float* ms  = tst + 1056;               // 1024
    __half* Ks  = (__half*)KV;
    __half* Vts = (__half*)KV;
    __half* Qs  = (__half*)qsf;

    const int i0 = blockIdx.x * TI;
    const int h  = blockIdx.y;
    const int b  = blockIdx.z;
    const int tid = threadIdx.x, lane = tid & 31, w = tid >> 5;
    const int r4 = lane >> 2, c2 = (lane & 3) * 2;

    // ---- phase 0: Qs, mask, transposed tdsm ----
    if (tid < 128) {
        int r = tid >> 3, dq = tid & 7;
        int4 v = ((const int4*)mqh)[(size_t)(b * SS + i0 + r) * 48 + h * 8 + dq];
        *(int4*)&Qs[r * 72 + dq * 8] = v;
    }
    {
        const int4* m4 = (const int4*)mask;
        int4 mm = m4[(size_t)(b * SS) / 4 + tid];
        ms[4 * tid + 0] = mm.x ? 1.f : 0.f;
        ms[4 * tid + 1] = mm.y ? 1.f : 0.f;
        ms[4 * tid + 2] = mm.z ? 1.f : 0.f;
        ms[4 * tid + 3] = mm.w ? 1.f : 0.f;
#pragma unroll
        for (int l = 0; l < 4; l++) {
            int j = tid + 256 * l;
            tst[(j >> 5) * 33 + (j & 31)] = tdsm[b * SS + j];
        }
    }
    __syncthreads();

    // ---- phase 1: scores = Q K^T via HMMA, masked, into transposed T ----
    for (int jt = 0; jt < 8; jt++) {
        const int j0 = jt * 128;
#pragma unroll
        for (int l = 0; l < 4; l++) {
            int e = tid + 256 * l;
            int j = e >> 3, dq = e & 7;
            int4 v = ((const int4*)mkh)[(size_t)(b * SS + j0 + j) * 48 + h * 8 + dq];
            *(int4*)&Ks[j * 72 + dq * 8] = v;
        }
        __syncthreads();
        float acc[2][4] = {};
#pragma unroll
        for (int kc = 0; kc < 4; kc++) {
            const int kk = kc * 16;
            unsigned a0 = *(const unsigned*)&Qs[r4 * 72 + kk + c2];
            unsigned a1 = *(const unsigned*)&Qs[(r4 + 8) * 72 + kk + c2];
            unsigned a2 = *(const unsigned*)&Qs[r4 * 72 + kk + c2 + 8];
            unsigned a3 = *(const unsigned*)&Qs[(r4 + 8) * 72 + kk + c2 + 8];
#pragma unroll
            for (int nf = 0; nf < 2; nf++) {
                int nr = 16 * w + 8 * nf + r4;
                unsigned b0 = *(const unsigned*)&Ks[nr * 72 + kk + c2];
                unsigned b1 = *(const unsigned*)&Ks[nr * 72 + kk + c2 + 8];
                float* d = acc[nf];
                asm volatile(
                    "mma.sync.aligned.m16n8k16.row.col.f32.f16.f16.f32 "
                    "{%0,%1,%2,%3}, {%4,%5,%6,%7}, {%8,%9}, {%0,%1,%2,%3};"
                    : "+f"(d[0]), "+f"(d[1]), "+f"(d[2]), "+f"(d[3])
                    : "r"(a0), "r"(a1), "r"(a2), "r"(a3), "r"(b0), "r"(b1));
            }
        }
#pragma unroll
        for (int nf = 0; nf < 2; nf++) {
            int j = j0 + 16 * w + 8 * nf + c2;
            int base = (j >> 5) * 33 + (j & 31);
            float m0 = ms[j], m1 = ms[j + 1];
            float s00 = m0 > 0.f ? acc[nf][0] * 0.125f : -1e8f;
            float s01 = m1 > 0.f ? acc[nf][1] * 0.125f : -1e8f;
            float s10 = m0 > 0.f ? acc[nf][2] * 0.125f : -1e8f;
            float s11 = m1 > 0.f ? acc[nf][3] * 0.125f : -1e8f;
            T[r4 * TP + base]           = s00;
            T[r4 * TP + base + 1]       = s01;
            T[(r4 + 8) * TP + base]     = s10;
            T[(r4 + 8) * TP + base + 1] = s11;
        }
        __syncthreads();
    }

    // ---- phase 2: per-row softmax -> cumsum -> rescore -> softmax -> Ph ----
    {
        float gm = gammas[h];
        float gamma = -((gm > 20.f) ? gm : log1pf(expf(gm)));
#pragma unroll 1
        for (int rr = 0; rr < 2; rr++) {
            const int r = 2 * w + rr;
            const int i = i0 + r;
            float* Trow = T + r * TP + lane * 33;
            float s[32], p[32];
#pragma unroll
            for (int t = 0; t < 32; t++) s[t] = Trow[t];
            float mx = s[0];
#pragma unroll
            for (int t = 1; t < 32; t++) mx = fmaxf(mx, s[t]);
#pragma unroll
            for (int o = 16; o; o >>= 1) mx = fmaxf(mx, __shfl_xor_sync(0xffffffffu, mx, o));
            float sum = 0.f;
#pragma unroll
            for (int t = 0; t < 32; t++) {
                p[t] = (s[t] > -1e7f) ? __expf(s[t] - mx) : 0.f;
                sum += p[t];
            }
#pragma unroll
            for (int o = 16; o; o >>= 1) sum += __shfl_xor_sync(0xffffffffu, sum, o);
            float inv = 1.f / sum;
            float run = 0.f;
#pragma unroll
            for (int t = 0; t < 32; t++) { run += p[t] * inv; p[t] = run; }
            float tot = run;
            float ex = tot;
#pragma unroll
            for (int d = 1; d < 32; d <<= 1) {
                float y = __shfl_up_sync(0xffffffffu, ex, d);
                if (lane >= d) ex += y;
            }
            float total = __shfl_sync(0xffffffffu, ex, 31);
            float excl = ex - tot;
#pragma unroll
            for (int t = 0; t < 32; t++) {
                if (s[t] > -1e7f) {
                    int j = lane * 32 + t;
                    float pos = fabsf((float)(j - i));
                    float rem = total - (excl + p[t]);
                    float ds = sqrtf(fmaxf(rem * pos, 0.f));
                    float te = fmaxf(__expf(ds * gamma), 1e-5f);
                    if (j < i) te -= tst[lane * 33 + t];
                    s[t] *= te;
                }
            }
            float mx2 = s[0];
#pragma unroll
            for (int t = 1; t < 32; t++) mx2 = fmaxf(mx2, s[t]);
#pragma unroll
            for (int o = 16; o; o >>= 1) mx2 = fmaxf(mx2, __shfl_xor_sync(0xffffffffu, mx2, o));
            float sum2 = 0.f;
#pragma unroll
            for (int t = 0; t < 32; t++) {
                p[t] = (s[t] > -1e7f) ? __expf(s[t] - mx2) : 0.f;
                sum2 += p[t];
            }
#pragma unroll
            for (int o = 16; o; o >>= 1) sum2 += __shfl_xor_sync(0xffffffffu, sum2, o);
            float inv2 = 1.f / sum2;
            // probs -> half, row-major (i, j); per-row shifted base for bank spread
            __half* Phr = (__half*)(T + r * TP + r * 4);
#pragma unroll
            for (int t2 = 0; t2 < 16; t2++) {
                int tt = (t2 + lane) & 15;
                *(__half2*)&Phr[lane * 32 + 2 * tt] =
                    __floats2half2_rn(p[2 * tt] * inv2, p[2 * tt + 1] * inv2);
            }
        }
    }
    __syncthreads();

    // ---- phase 3: ctx = P V via HMMA (V transposed in smem) ----
    float acc[4] = {0.f, 0.f, 0.f, 0.f};
    const __half* Pr0 = (const __half*)(T + r4 * TP + r4 * 4);
    const __half* Pr8 = (const __half*)(T + (r4 + 8) * TP + (r4 + 8) * 4);
    for (int jt = 0; jt < 8; jt++) {
        const int j0 = jt * 128;
#pragma unroll
        for (int l = 0; l < 16; l++) {
            int e = tid + 256 * l;
            int j = e >> 5, dp = e & 31;
            __half2 v = ((const __half2*)mvh)[(size_t)(b * SS + j0 + j) * 192 + h * 32 + dp];
            Vts[(2 * dp) * 138 + j]     = __low2half(v);
            Vts[(2 * dp + 1) * 138 + j] = __high2half(v);
        }
        __syncthreads();
#pragma unroll
        for (int kc = 0; kc < 8; kc++) {
            const int kg = j0 + kc * 16;   // global j for probs
            const int kl = kc * 16;        // local j for Vts
            unsigned a0 = *(const unsigned*)&Pr0[kg + c2];
            unsigned a1 = *(const unsigned*)&Pr8[kg + c2];
            unsigned a2 = *(const unsigned*)&Pr0[kg + c2 + 8];
            unsigned a3 = *(const unsigned*)&Pr8[kg + c2 + 8];
            int nr = 8 * w + r4;
            unsigned b0 = *(const unsigned*)&Vts[nr * 138 + kl + c2];
            unsigned b1 = *(const unsigned*)&Vts[nr * 138 + kl + c2 + 8];
            asm volatile(
                "mma.sync.aligned.m16n8k16.row.col.f32.f16.f16.f32 "
                "{%0,%1,%2,%3}, {%4,%5,%6,%7}, {%8,%9}, {%0,%1,%2,%3};"
                : "+f"(acc[0]), "+f"(acc[1]), "+f"(acc[2]), "+f"(acc[3])
                : "r"(a0), "r"(a1), "r"(a2), "r"(a3), "r"(b0), "r"(b1));
        }
        __syncthreads();
    }
    {
        int dc = h * DDIM + 8 * w + c2;
        size_t o0 = (size_t)(b * SS + i0 + r4) * 768 + dc;
        size_t o1 = (size_t)(b * SS + i0 + r4 + 8) * 768 + dc;
        *(float2*)&out[o0] = make_float2(acc[0], acc[1]);
        *(float2*)&out[o1] = make_float2(acc[2], acc[3]);
    }
}

// ---------------- launch ----------------------------------------------------
extern "C" void kernel_launch(void* const* d_in, const int* in_sizes, int n_in,
                              void* d_out, int out_size) {
    const float* Q    = (const float*)d_in[0];
    const float* Kin  = (const float*)d_in[1];
    const float* V    = (const float*)d_in[2];
    const float* td   = (const float*)d_in[3];
    const int*   mask = (const int*)  d_in[4];
    const float* Wq   = (const float*)d_in[5];
    const float* Wk   = (const float*)d_in[6];
    const float* Wv   = (const float*)d_in[7];
    const float* dw_w = (const float*)d_in[8];
    const float* pw_w = (const float*)d_in[9];
    const float* sep_b= (const float*)d_in[10];
    const float* ck_W = (const float*)d_in[11];
    const float* ck_b = (const float*)d_in[12];
    const float* co_W = (const float*)d_in[13];
    const float* co_b = (const float*)d_in[14];
    const float* gammas=(const float*)d_in[15];
    float* out = (float*)d_out;

    float *mq, *co, *mkc, *ca, *ck, *tdsm;
    __half *Qh, *Kh, *Vh, *dwh, *WqT, *WkT, *WvT, *coT, *pwh, *mqh, *mkh, *mvh;
    cudaGetSymbolAddress((void**)&mq,  g_mq);
    cudaGetSymbolAddress((void**)&co,  g_co);
    cudaGetSymbolAddress((void**)&mkc, g_mkc);
    cudaGetSymbolAddress((void**)&ca,  g_ca);
    cudaGetSymbolAddress((void**)&ck,  g_ck);
    cudaGetSymbolAddress((void**)&tdsm,g_tdsm);
    cudaGetSymbolAddress((void**)&Qh,  g_Qh);
    cudaGetSymbolAddress((void**)&Kh,  g_Kh);
    cudaGetSymbolAddress((void**)&Vh,  g_Vh);
    cudaGetSymbolAddress((void**)&dwh, g_dwh);
    cudaGetSymbolAddress((void**)&WqT, g_WqT);
    cudaGetSymbolAddress((void**)&WkT, g_WkT);
    cudaGetSymbolAddress((void**)&WvT, g_WvT);
    cudaGetSymbolAddress((void**)&coT, g_coT);
    cudaGetSymbolAddress((void**)&pwh, g_pwh);
    cudaGetSymbolAddress((void**)&mqh, g_mqh);
    cudaGetSymbolAddress((void**)&mkh, g_mkh);
    cudaGetSymbolAddress((void**)&mvh, g_mvh);

    static int smem_set = 0;
    const int attn_smem = (TI * TP + 4608 + 576 + 1056 + 1024) * 4;  // 97152 B
    if (!smem_set) {
        cudaFuncSetAttribute(attn_kernel, cudaFuncAttributeMaxDynamicSharedMemorySize,
                             attn_smem);
        smem_set = 1;
    }

    // ---- pack: fp32 -> fp16 ----
    const int nQKV4 = NROWS * HIDN / 4;
    convert_kernel<<<(nQKV4 + 255) / 256, 256>>>(Q,   Qh, nQKV4);
    convert_kernel<<<(nQKV4 + 255) / 256, 256>>>(Kin, Kh, nQKV4);
    convert_kernel<<<(nQKV4 + 255) / 256, 256>>>(V,   Vh, nQKV4);
    const int nW4 = AHN * HIDN / 4;
    convert_kernel<<<(nW4 + 255) / 256, 256>>>(pw_w, pwh, nW4);
    dim3 tB(32, 8), tG(AHN / 32, HIDN / 32);
    transconv_kernel<<<tG, tB>>>(Wq,   WqT, HIDN, AHN);
    transconv_kernel<<<tG, tB>>>(Wk,   WkT, HIDN, AHN);
    transconv_kernel<<<tG, tB>>>(Wv,   WvT, HIDN, AHN);
    transconv_kernel<<<tG, tB>>>(co_W, coT, HIDN, AHN);

    dwconv_kernel<<<(NROWS * HIDN + 255) / 256, 256>>>(Kin, dw_w, dwh);

    // ---- 5 big GEMMs, one launch; mq dual fp32+fp16, mk/mv fp16 only ----
    JobsH jh;
    jh.A[0] = Qh;  jh.B[0] = WqT; jh.bias[0] = nullptr; jh.C[0] = mq;     jh.Ch[0] = mqh;
    jh.A[1] = Kh;  jh.B[1] = WkT; jh.bias[1] = nullptr; jh.C[1] = nullptr;jh.Ch[1] = mkh;
    jh.A[2] = Vh;  jh.B[2] = WvT; jh.bias[2] = nullptr; jh.C[2] = nullptr;jh.Ch[2] = mvh;
    jh.A[3] = Vh;  jh.B[3] = coT; jh.bias[3] = co_b;    jh.C[3] = co;     jh.Ch[3] = nullptr;
    jh.A[4] = dwh; jh.B[4] = pwh; jh.bias[4] = sep_b;   jh.C[4] = mkc;    jh.Ch[4] = nullptr;
    hgemm<<<dim3(AHN / 128, NROWS / 128, 5), 256>>>(jh, NROWS, AHN, HIDN);

    emul_kernel<<<(NROWS * AHN + 255) / 256, 256>>>(mkc, mq, ca, NROWS * AHN);
    sgemm_small<false, true><<<dim3(1, NROWS / 64), 256>>>(ca, ck_W, ck_b, ck,
                                                           NROWS, NH * KSZ, AHN);
    ck_softmax_kernel<<<(NROWS * NH + 255) / 256, 256>>>(ck);
    conv_out_kernel<<<NROWS, AHN>>>(co, ck, out);

    tdsm_kernel<<<BB, 256>>>(td, mask, tdsm);
    attn_kernel<<<dim3(SS / TI, NH, BB), 256, attn_smem>>>(mqh, mkh, mvh, mask, tdsm,
                                                           gammas, out);
}